// round 1
// baseline (speedup 1.0000x reference)
#include <cuda_runtime.h>
#include <math.h>

#define IMGW 128
#define NA   60
#define NPIX 7680           /* 60*128 */
#define NP   625
#define C1C  32
#define C2C  64

/* ---------------- scratch (static device memory; no allocs) -------------- */
__device__ float g_c1[NP * C1C * NPIX];                 /* 614 MB  */
__device__ float g_c2[NP * C2C * NPIX];                 /* 1229 MB */
__device__ float g_w2p[C1C * 9 * C2C];                  /* conv2 w transposed [ci*9+k][co] */
__device__ float g_patches[NP * 25];

typedef unsigned long long u64;

__device__ __forceinline__ u64 dup2(float v) {
    u64 r; asm("mov.b64 %0,{%1,%1};" : "=l"(r) : "f"(v)); return r;
}
__device__ __forceinline__ void fma2(u64 &d, u64 a, u64 b) {
    asm("fma.rn.f32x2 %0,%1,%2,%0;" : "+l"(d) : "l"(a), "l"(b));
}
__device__ __forceinline__ float2 unpk(u64 v) {
    float2 r; asm("mov.b64 {%0,%1},%2;" : "=f"(r.x), "=f"(r.y) : "l"(v)); return r;
}

/* -------------------- weight transpose for conv2 ------------------------- */
__global__ void prep_w2_kernel(const float* __restrict__ w2) {
    int i = blockIdx.x * blockDim.x + threadIdx.x;
    if (i < C2C * C1C * 9) {
        int co = i / (C1C * 9);
        int r  = i - co * (C1C * 9);
        int ci = r / 9;
        int k  = r - ci * 9;
        g_w2p[(ci * 9 + k) * C2C + co] = w2[i];
    }
}

/* ------------------- conv1: mask*sino -> 32ch, relu ---------------------- */
__global__ __launch_bounds__(256) void conv1_kernel(
    const float* __restrict__ sino, const int* __restrict__ masks,
    const float* __restrict__ w1, const float* __restrict__ b1)
{
    __shared__ float img[62 * 132];
    __shared__ float ws[288];
    __shared__ float bs[32];
    int p = blockIdx.x, tid = threadIdx.x;

    for (int i = tid; i < 62 * 132; i += 256) img[i] = 0.f;
    for (int i = tid; i < 288; i += 256) ws[i] = w1[i];
    if (tid < 32) bs[tid] = b1[tid];
    __syncthreads();
    const int* mp = masks + p * NPIX;
    for (int i = tid; i < NPIX; i += 256) {
        int y = i >> 7, x = i & 127;
        img[(y + 1) * 132 + (x + 1)] = sino[i] * (float)mp[i];
    }
    __syncthreads();

    float* outp = g_c1 + (size_t)p * C1C * NPIX;
    for (int co = 0; co < C1C; ++co) {
        float wr[9];
#pragma unroll
        for (int k = 0; k < 9; ++k) wr[k] = ws[co * 9 + k];
        float bc = bs[co];
        for (int i = tid; i < NPIX; i += 256) {
            int y = i >> 7, x = i & 127;
            const float* base = img + y * 132 + x;
            float s = bc;
#pragma unroll
            for (int dy = 0; dy < 3; ++dy)
#pragma unroll
                for (int dx = 0; dx < 3; ++dx)
                    s += wr[dy * 3 + dx] * base[dy * 132 + dx];
            outp[co * NPIX + i] = fmaxf(s, 0.f);
        }
    }
}

/* ---------------- conv2: 32->64, relu — f32x2 packed FMA ----------------- */
/* block: (row-tile of 2, image). 512 thr. smem: w [ci*9+k][64] + in [32][4][132] */
#define C2_SMEM_BYTES (18432 * 4 + 32 * 4 * 132 * 4)   /* 141312 */

__global__ __launch_bounds__(512) void conv2_kernel(const float* __restrict__ b2)
{
    extern __shared__ float sm[];
    float* s_w  = sm;            /* 18432 */
    float* s_in = sm + 18432;    /* 32*4*132 */
    int p  = blockIdx.y;
    int y0 = blockIdx.x * 2;
    int tid = threadIdx.x;

    for (int i = tid; i < 18432; i += 512) s_w[i] = g_w2p[i];
    const float* c1p = g_c1 + (size_t)p * C1C * NPIX;
    for (int i = tid; i < 32 * 4 * 130; i += 512) {
        int ci  = i / 520;
        int rem = i - ci * 520;
        int r   = rem / 130;
        int xc  = rem - r * 130;
        int y = y0 - 1 + r, x = xc - 1;
        float v = 0.f;
        if (x >= 0 && x < 128 && y >= 0 && y < 60) v = c1p[(ci * 60 + y) * 128 + x];
        s_in[(ci * 4 + r) * 132 + xc] = v;
    }
    __syncthreads();

    int yl = tid >> 8;                 /* 0..1 */
    int cobase = ((tid >> 5) & 7) * 8; /* 8 co per thread */
    int x0 = (tid & 31) * 4;

    u64 acc[4][4];
#pragma unroll
    for (int c = 0; c < 4; ++c)
#pragma unroll
        for (int x = 0; x < 4; ++x) acc[c][x] = 0ULL;

    for (int ci = 0; ci < 32; ++ci) {
        const float* ib = s_in + (ci * 4 + yl) * 132 + x0;
        const float* wb = s_w + ci * 9 * C2C + cobase;
#pragma unroll
        for (int dy = 0; dy < 3; ++dy) {
            float4 A = *(const float4*)(ib + dy * 132);
            float4 B = *(const float4*)(ib + dy * 132 + 4);
            u64 dv[6];
            dv[0] = dup2(A.x); dv[1] = dup2(A.y); dv[2] = dup2(A.z);
            dv[3] = dup2(A.w); dv[4] = dup2(B.x); dv[5] = dup2(B.y);
#pragma unroll
            for (int dx = 0; dx < 3; ++dx) {
                const u64* wp = (const u64*)(wb + (dy * 3 + dx) * C2C);
                u64 w0 = wp[0], w1 = wp[1], w2 = wp[2], w3 = wp[3];
#pragma unroll
                for (int x = 0; x < 4; ++x) {
                    fma2(acc[0][x], w0, dv[dx + x]);
                    fma2(acc[1][x], w1, dv[dx + x]);
                    fma2(acc[2][x], w2, dv[dx + x]);
                    fma2(acc[3][x], w3, dv[dx + x]);
                }
            }
        }
    }

    int yo = y0 + yl;
    float* ob = g_c2 + (((size_t)p * C2C + cobase) * 60 + yo) * 128 + x0;
#pragma unroll
    for (int cp = 0; cp < 4; ++cp) {
        float blo = __ldg(&b2[cobase + 2 * cp]);
        float bhi = __ldg(&b2[cobase + 2 * cp + 1]);
        float2 u0 = unpk(acc[cp][0]), u1 = unpk(acc[cp][1]);
        float2 u2 = unpk(acc[cp][2]), u3 = unpk(acc[cp][3]);
        float4 lo4 = make_float4(fmaxf(u0.x + blo, 0.f), fmaxf(u1.x + blo, 0.f),
                                 fmaxf(u2.x + blo, 0.f), fmaxf(u3.x + blo, 0.f));
        float4 hi4 = make_float4(fmaxf(u0.y + bhi, 0.f), fmaxf(u1.y + bhi, 0.f),
                                 fmaxf(u2.y + bhi, 0.f), fmaxf(u3.y + bhi, 0.f));
        *(float4*)(ob + (size_t)(2 * cp) * NPIX)     = lo4;
        *(float4*)(ob + (size_t)(2 * cp + 1) * NPIX) = hi4;
    }
}

/* ------------- conv3 (64->1) + linear (7680 -> 25), fused per image ------ */
#define C3_SMEM_BYTES ((8184 + 7680 + 576) * 4)   /* 65760 */

__global__ __launch_bounds__(256) void conv3lin_kernel(
    const float* __restrict__ w3, const float* __restrict__ b3,
    const float* __restrict__ linw, const float* __restrict__ linb)
{
    extern __shared__ float sm[];
    float* plane = sm;          /* 62*132 padded */
    float* cs    = sm + 8184;   /* 7680 */
    float* w3s   = cs + 7680;   /* 576 */
    int p = blockIdx.x, tid = threadIdx.x;

    for (int i = tid; i < 576; i += 256) w3s[i] = w3[i];
    for (int i = tid; i < 8184; i += 256) plane[i] = 0.f;

    float acc[30];
#pragma unroll
    for (int j = 0; j < 30; ++j) acc[j] = 0.f;

    const float* c2p = g_c2 + (size_t)p * C2C * NPIX;
    for (int ci = 0; ci < C2C; ++ci) {
        __syncthreads();
        for (int i = tid; i < NPIX; i += 256)
            plane[((i >> 7) + 1) * 132 + (i & 127) + 1] = c2p[ci * NPIX + i];
        __syncthreads();
        float wr[9];
#pragma unroll
        for (int k = 0; k < 9; ++k) wr[k] = w3s[ci * 9 + k];
#pragma unroll
        for (int j = 0; j < 30; ++j) {
            int i = tid + 256 * j;
            int y = i >> 7, x = i & 127;
            const float* base = plane + y * 132 + x;
            float s = acc[j];
#pragma unroll
            for (int dy = 0; dy < 3; ++dy)
#pragma unroll
                for (int dx = 0; dx < 3; ++dx)
                    s += wr[dy * 3 + dx] * base[dy * 132 + dx];
            acc[j] = s;
        }
    }
    __syncthreads();
    float b3v = __ldg(&b3[0]);
#pragma unroll
    for (int j = 0; j < 30; ++j) cs[tid + 256 * j] = acc[j] + b3v;
    __syncthreads();

    int warp = tid >> 5, lane = tid & 31;
    for (int k = warp; k < 25; k += 8) {
        const float* wk = linw + k * NPIX;
        float s = 0.f;
        for (int n = lane; n < NPIX; n += 32) s += cs[n] * __ldg(&wk[n]);
#pragma unroll
        for (int off = 16; off > 0; off >>= 1) s += __shfl_down_sync(0xffffffffu, s, off);
        if (lane == 0) g_patches[p * 25 + k] = s + __ldg(&linb[k]);
    }
}

/* -------------------- recon: fill 0.5 then scatter sigmoid --------------- */
__global__ void fill_kernel(float* __restrict__ out) {
    int i = blockIdx.x * blockDim.x + threadIdx.x;
    if (i < IMGW * IMGW) out[i] = 0.5f;
}
__global__ void scatter_kernel(const int* __restrict__ starts, float* __restrict__ out) {
    int t = blockIdx.x * blockDim.x + threadIdx.x;
    if (t >= NP * 25) return;
    int p = t / 25, q = t - p * 25;
    int i = starts[2 * p] + q / 5;
    int j = starts[2 * p + 1] + q % 5;
    float v = g_patches[t];
    out[i * IMGW + j] = 1.f / (1.f + expf(-v));
}

/* -------------------------------- radon ---------------------------------- */
__global__ __launch_bounds__(128) void radon_kernel(float* __restrict__ out) {
    int a = blockIdx.x, tid = threadIdx.x;
    double ang = (double)a * (M_PI / 180.0);
    float ct = (float)cos(ang), st = (float)sin(ang);
    float t = (float)tid - 63.5f;
    const float* img = out;   /* y_hat region */
    float accum = 0.f;
    for (int ss = 0; ss < 128; ++ss) {
        float s = (float)ss - 63.5f;
        float x = 63.5f + t * ct - s * st;
        float y = 63.5f + t * st + s * ct;
        float fx = floorf(x), fy = floorf(y);
        int x0 = (int)fx, y0 = (int)fy;
        float wx = x - fx, wy = y - fy;
        float v00 = 0.f, v10 = 0.f, v01 = 0.f, v11 = 0.f;
        if (x0 >= 0 && x0 < 128 && y0 >= 0 && y0 < 128)         v00 = __ldg(&img[y0 * 128 + x0]);
        if (x0 + 1 >= 0 && x0 + 1 < 128 && y0 >= 0 && y0 < 128) v10 = __ldg(&img[y0 * 128 + x0 + 1]);
        if (x0 >= 0 && x0 < 128 && y0 + 1 >= 0 && y0 + 1 < 128) v01 = __ldg(&img[(y0 + 1) * 128 + x0]);
        if (x0 + 1 >= 0 && x0 + 1 < 128 && y0 + 1 >= 0 && y0 + 1 < 128)
            v11 = __ldg(&img[(y0 + 1) * 128 + x0 + 1]);
        accum += v00 * (1.f - wx) * (1.f - wy) + v10 * wx * (1.f - wy)
               + v01 * (1.f - wx) * wy + v11 * wx * wy;
    }
    out[IMGW * IMGW + a * 128 + tid] = accum;
}

/* ------------------------------- launch ---------------------------------- */
extern "C" void kernel_launch(void* const* d_in, const int* in_sizes, int n_in,
                              void* d_out, int out_size)
{
    const float* sino   = (const float*)d_in[0];
    const float* w1     = (const float*)d_in[1];
    const float* b1     = (const float*)d_in[2];
    const float* w2     = (const float*)d_in[3];
    const float* b2     = (const float*)d_in[4];
    const float* w3     = (const float*)d_in[5];
    const float* b3     = (const float*)d_in[6];
    const float* linw   = (const float*)d_in[7];
    const float* linb   = (const float*)d_in[8];
    const int*   masks  = (const int*)d_in[9];
    const int*   starts = (const int*)d_in[10];
    float* out = (float*)d_out;

    cudaFuncSetAttribute(conv2_kernel, cudaFuncAttributeMaxDynamicSharedMemorySize, C2_SMEM_BYTES);
    cudaFuncSetAttribute(conv3lin_kernel, cudaFuncAttributeMaxDynamicSharedMemorySize, C3_SMEM_BYTES);

    prep_w2_kernel<<<(C2C * C1C * 9 + 255) / 256, 256>>>(w2);
    conv1_kernel<<<NP, 256>>>(sino, masks, w1, b1);
    conv2_kernel<<<dim3(30, NP), 512, C2_SMEM_BYTES>>>(b2);
    conv3lin_kernel<<<NP, 256, C3_SMEM_BYTES>>>(w3, b3, linw, linb);
    fill_kernel<<<(IMGW * IMGW + 255) / 256, 256>>>(out);
    scatter_kernel<<<(NP * 25 + 255) / 256, 256>>>(starts, out);
    radon_kernel<<<NA, 128>>>(out);
}

// round 2
// speedup vs baseline: 1.3259x; 1.3259x over previous
#include <cuda_runtime.h>
#include <math.h>

#define IMGW 128
#define NA   60
#define NPIX 7680
#define NP   625
#define C1C  32
#define C2C  64
#define W    32

/* ---------------- scratch (static device memory) ------------------------- */
__device__ float g_y1s[(size_t)NP * C1C * NA * W];   /* 153.6 MB strips */
__device__ float g_y2s[(size_t)NP * C2C * NA * W];   /* 307 MB strips   */
__device__ float g_y3s[NP * NA * W];                 /* 4.8 MB          */
__device__ int   g_anchor[NP * NA];
__device__ int   g_nz[NP];
__device__ float g_w2p[C1C * 9 * C2C];
__device__ float g_c1[C1C];
__device__ float g_bg2c[9 * C2C];
__device__ float g_bg3[NPIX];
__device__ float g_xbg[25];
__device__ float g_patches[NP * 25];

typedef unsigned long long u64;
__device__ __forceinline__ u64 dup2(float v) {
    u64 r; asm("mov.b64 %0,{%1,%1};" : "=l"(r) : "f"(v)); return r;
}
__device__ __forceinline__ void fma2(u64 &d, u64 a, u64 b) {
    asm("fma.rn.f32x2 %0,%1,%2,%0;" : "+l"(d) : "l"(a), "l"(b));
}
__device__ __forceinline__ float2 unpk(u64 v) {
    float2 r; asm("mov.b64 {%0,%1},%2;" : "=f"(r.x), "=f"(r.y) : "l"(v)); return r;
}

/* ------------------------- weight transpose ------------------------------ */
__global__ void prep_w2_kernel(const float* __restrict__ w2) {
    int i = blockIdx.x * blockDim.x + threadIdx.x;
    if (i < C2C * C1C * 9) {
        int co = i / (C1C * 9);
        int r  = i - co * (C1C * 9);
        int ci = r / 9;
        int k  = r - ci * 9;
        g_w2p[(ci * 9 + k) * C2C + co] = w2[i];
    }
}

/* -------------- background constants: c1, y2_bg classes ------------------ */
__global__ void prep_small_kernel(const float* __restrict__ w2,
                                  const float* __restrict__ b1,
                                  const float* __restrict__ b2) {
    __shared__ float c1s[32];
    int t = threadIdx.x;
    if (t < 32) { float v = fmaxf(b1[t], 0.f); c1s[t] = v; g_c1[t] = v; }
    __syncthreads();
    if (t < 576) {
        int co = t & 63, cls = t >> 6;
        int ry = cls / 3, rx = cls - ry * 3;
        float s = b2[co];
        for (int ci = 0; ci < 32; ++ci) {
            float wsum = 0.f;
            for (int dy = 0; dy < 3; ++dy) {
                if (ry == 0 && dy == 0) continue;
                if (ry == 2 && dy == 2) continue;
                for (int dx = 0; dx < 3; ++dx) {
                    if (rx == 0 && dx == 0) continue;
                    if (rx == 2 && dx == 2) continue;
                    wsum += w2[co * 288 + ci * 9 + dy * 3 + dx];
                }
            }
            s += wsum * c1s[ci];
        }
        g_bg2c[cls * 64 + co] = fmaxf(s, 0.f);
    }
}

/* ------------------------- y3 background field --------------------------- */
__global__ void bg3_kernel(const float* __restrict__ w3, const float* __restrict__ b3) {
    __shared__ float bg2s[576];
    int a = blockIdx.x, x = threadIdx.x;
    for (int i = x; i < 576; i += 128) bg2s[i] = g_bg2c[i];
    __syncthreads();
    float s = b3[0];
    for (int dy = 0; dy < 3; ++dy) {
        int aa = a + dy - 1; if (aa < 0 || aa >= 60) continue;
        int ry = (aa == 0) ? 0 : ((aa == 59) ? 2 : 1);
        for (int dx = 0; dx < 3; ++dx) {
            int xx = x + dx - 1; if (xx < 0 || xx >= 128) continue;
            int rx = (xx == 0) ? 0 : ((xx == 127) ? 2 : 1);
            const float* cp = bg2s + (ry * 3 + rx) * 64;
            int k = dy * 3 + dx;
            for (int ci = 0; ci < 64; ++ci) s += w3[ci * 9 + k] * cp[ci];
        }
    }
    g_bg3[a * 128 + x] = s;
}

/* ---------------------- x_bg = lin(y3_bg) -------------------------------- */
__global__ void xbg_kernel(const float* __restrict__ linw, const float* __restrict__ linb) {
    __shared__ float bg[NPIX];
    int t = threadIdx.x;
    for (int i = t; i < NPIX; i += 256) bg[i] = g_bg3[i];
    __syncthreads();
    int warp = t >> 5, lane = t & 31;
    for (int k = warp; k < 25; k += 8) {
        const float* wk = linw + k * NPIX;
        float s = 0.f;
        for (int n = lane; n < NPIX; n += 32) s += bg[n] * __ldg(&wk[n]);
        for (int o = 16; o; o >>= 1) s += __shfl_down_sync(0xffffffffu, s, o);
        if (!lane) g_xbg[k] = s + linb[k];
    }
}

/* --------------------------- anchors + nz flag --------------------------- */
__global__ void anchors_kernel(const int* __restrict__ masks) {
    __shared__ int nzf;
    int p = blockIdx.x, t = threadIdx.x;
    if (t == 0) nzf = 0;
    __syncthreads();
    if (t < 60) {
        const int* mp = masks + p * NPIX + t * 128;
        int L = -1, R = -1;
        for (int x = 0; x < 128; x += 4) {
            int4 m = *(const int4*)(mp + x);
            if (m.x) { if (L < 0) L = x;     R = x; }
            if (m.y) { if (L < 0) L = x + 1; R = x + 1; }
            if (m.z) { if (L < 0) L = x + 2; R = x + 2; }
            if (m.w) { if (L < 0) L = x + 3; R = x + 3; }
        }
        int anc;
        if (L < 0) anc = 48;
        else {
            nzf = 1;
            int c = (L + R) >> 1;
            anc = c - 16; if (anc < 0) anc = 0; if (anc > 96) anc = 96;
        }
        g_anchor[p * 60 + t] = anc;
    }
    __syncthreads();
    if (t == 0) g_nz[p] = nzf;
}

/* ----------------------- conv1 on strips --------------------------------- */
__global__ __launch_bounds__(256) void conv1s_kernel(
    const float* __restrict__ sino, const int* __restrict__ masks,
    const float* __restrict__ w1, const float* __restrict__ b1)
{
    int p = blockIdx.x;
    if (!g_nz[p]) return;
    __shared__ float w1s[288], b1s[32];
    __shared__ int anch[60];
    int t = threadIdx.x;
    for (int i = t; i < 288; i += 256) w1s[i] = w1[i];
    if (t < 32) b1s[t] = b1[t];
    if (t < 60) anch[t] = g_anchor[p * 60 + t];
    __syncthreads();
    const int* mp = masks + p * NPIX;
    for (int e = t; e < NA * W; e += 256) {
        int a = e >> 5, u = e & 31;
        int x = anch[a] + u;
        float tap[9];
#pragma unroll
        for (int dy = 0; dy < 3; ++dy) {
            int aa = a + dy - 1;
#pragma unroll
            for (int dx = 0; dx < 3; ++dx) {
                int xx = x + dx - 1;
                float v = 0.f;
                if (aa >= 0 && aa < 60 && xx >= 0 && xx < 128) {
                    int ii = aa * 128 + xx;
                    v = sino[ii] * (float)mp[ii];
                }
                tap[dy * 3 + dx] = v;
            }
        }
        float* op = g_y1s + (size_t)p * (C1C * NA * W) + e;
        for (int ci = 0; ci < 32; ++ci) {
            float s = b1s[ci];
#pragma unroll
            for (int k = 0; k < 9; ++k) s += w1s[ci * 9 + k] * tap[k];
            op[(size_t)ci * (NA * W)] = fmaxf(s, 0.f);
        }
    }
}

/* ----------------------- conv2 on strips (f32x2) ------------------------- */
#define C2S_SMEM ((18432 + 32 * 8 * 64 + 32 + 8) * 4)

__global__ __launch_bounds__(384) void conv2s_kernel(const float* __restrict__ b2)
{
    int p = blockIdx.y;
    if (!g_nz[p]) return;
    extern __shared__ float sm[];
    float* s_w  = sm;                 /* 18432 */
    float* y1h  = sm + 18432;         /* 32*8*64 = 16384 */
    float* c1s  = y1h + 16384;        /* 32 */
    int*   anch = (int*)(c1s + 32);   /* 8  */
    int r0 = blockIdx.x * 6;
    int tid = threadIdx.x;

    if (tid < 8) {
        int a = r0 - 1 + tid; a = a < 0 ? 0 : (a > 59 ? 59 : a);
        anch[tid] = g_anchor[p * 60 + a];
    }
    if (tid >= 8 && tid < 40) c1s[tid - 8] = g_c1[tid - 8];
    for (int i = tid; i < 18432; i += 384) s_w[i] = g_w2p[i];
    __syncthreads();

    int base = anch[0];
#pragma unroll
    for (int i = 1; i < 8; ++i) base = min(base, anch[i]);
    base -= 2;

    const float* y1p = g_y1s + (size_t)p * (C1C * NA * W);
    for (int i = tid; i < 16384; i += 384) {
        int ci = i >> 9, r = (i >> 6) & 7, x = (i & 63) + base;
        int a = r0 - 1 + r;
        float v = 0.f;
        if (a >= 0 && a < 60 && x >= 0 && x < 128) {
            int u = x - anch[r];
            v = (u >= 0 && u < 32) ? y1p[ci * (NA * W) + a * 32 + u] : c1s[ci];
        }
        y1h[i] = v;
    }
    __syncthreads();

    int rr = tid / 64;                 /* 0..5 */
    int co_grp = (tid >> 3) & 7;
    int u0 = (tid & 7) * 4;
    int a = r0 + rr;
    int off = anch[rr + 1] - base;

    u64 acc[4][4];
#pragma unroll
    for (int c = 0; c < 4; ++c)
#pragma unroll
        for (int x = 0; x < 4; ++x) acc[c][x] = 0ULL;

    for (int ci = 0; ci < 32; ++ci) {
        const float* ibase = y1h + (ci * 8 + rr) * 64 + off + u0 - 1;
#pragma unroll
        for (int dy = 0; dy < 3; ++dy) {
            const float* row = ibase + dy * 64;
            u64 dv[6];
            dv[0] = dup2(row[0]); dv[1] = dup2(row[1]); dv[2] = dup2(row[2]);
            dv[3] = dup2(row[3]); dv[4] = dup2(row[4]); dv[5] = dup2(row[5]);
#pragma unroll
            for (int dx = 0; dx < 3; ++dx) {
                const u64* wp = (const u64*)(s_w + (ci * 9 + dy * 3 + dx) * 64 + co_grp * 8);
                u64 w0 = wp[0], w1 = wp[1], w2 = wp[2], w3 = wp[3];
#pragma unroll
                for (int xq = 0; xq < 4; ++xq) {
                    fma2(acc[0][xq], w0, dv[dx + xq]);
                    fma2(acc[1][xq], w1, dv[dx + xq]);
                    fma2(acc[2][xq], w2, dv[dx + xq]);
                    fma2(acc[3][xq], w3, dv[dx + xq]);
                }
            }
        }
    }

    int cobase = co_grp * 8;
    float* ob = g_y2s + ((size_t)p * C2C + cobase) * (NA * W) + a * 32 + u0;
#pragma unroll
    for (int cp = 0; cp < 4; ++cp) {
        float blo = __ldg(&b2[cobase + 2 * cp]);
        float bhi = __ldg(&b2[cobase + 2 * cp + 1]);
        float2 u0v = unpk(acc[cp][0]), u1v = unpk(acc[cp][1]);
        float2 u2v = unpk(acc[cp][2]), u3v = unpk(acc[cp][3]);
        float4 lo4 = make_float4(fmaxf(u0v.x + blo, 0.f), fmaxf(u1v.x + blo, 0.f),
                                 fmaxf(u2v.x + blo, 0.f), fmaxf(u3v.x + blo, 0.f));
        float4 hi4 = make_float4(fmaxf(u0v.y + bhi, 0.f), fmaxf(u1v.y + bhi, 0.f),
                                 fmaxf(u2v.y + bhi, 0.f), fmaxf(u3v.y + bhi, 0.f));
        *(float4*)(ob + (size_t)(2 * cp) * (NA * W))     = lo4;
        *(float4*)(ob + (size_t)(2 * cp + 1) * (NA * W)) = hi4;
    }
}

/* ----------------------- conv3 on strips --------------------------------- */
#define C3S_SMEM ((64 * 8 * 48 + 576 + 576 + 64) * 4)

__global__ __launch_bounds__(256) void conv3s_kernel(
    const float* __restrict__ w3, const float* __restrict__ b3)
{
    int p = blockIdx.x;
    if (!g_nz[p]) return;
    extern __shared__ float sm[];
    float* y2h = sm;                  /* 24576 */
    float* w3s = sm + 24576;          /* 576 */
    float* bgc = w3s + 576;           /* 576 */
    int*  anch = (int*)(bgc + 576);   /* 60  */
    int t = threadIdx.x;
    for (int i = t; i < 576; i += 256) { w3s[i] = w3[i]; bgc[i] = g_bg2c[i]; }
    if (t < 60) anch[t] = g_anchor[p * 60 + t];
    float b3v = __ldg(&b3[0]);
    const float* y2p = g_y2s + (size_t)p * C2C * (NA * W);

    for (int c0 = 0; c0 < 60; c0 += 6) {
        __syncthreads();
        for (int i = t; i < 64 * 8 * 48; i += 256) {
            int ci = i / 384, rem = i - ci * 384;
            int r = rem / 48, xi = rem - r * 48;
            int a = c0 - 1 + r;
            float v = 0.f;
            if (a >= 0 && a < 60) {
                int u = xi - 8;
                int x = anch[a] + u;
                if (x >= 0 && x < 128) {
                    if (u >= 0 && u < 32) v = y2p[ci * (NA * W) + a * 32 + u];
                    else {
                        int ry = (a == 0) ? 0 : ((a == 59) ? 2 : 1);
                        int rx = (x == 0) ? 0 : ((x == 127) ? 2 : 1);
                        v = bgc[(ry * 3 + rx) * 64 + ci];
                    }
                }
            }
            y2h[i] = v;
        }
        __syncthreads();
        if (t < 192) {
            int r = t >> 5, u = t & 31;
            int a = c0 + r;
            int anca = anch[a];
            float s = b3v;
#pragma unroll
            for (int dy = 0; dy < 3; ++dy) {
                int ar = a - 1 + dy;
                int du = anca - ((ar >= 0 && ar < 60) ? anch[ar] : anca);
                int bi = 8 + du + u - 1;
                if (bi < 0) bi = 0; if (bi > 45) bi = 45;
                for (int ci = 0; ci < 64; ++ci) {
                    const float* rp = y2h + (ci * 8 + r + dy) * 48 + bi;
                    s += w3s[ci * 9 + dy * 3 + 0] * rp[0]
                       + w3s[ci * 9 + dy * 3 + 1] * rp[1]
                       + w3s[ci * 9 + dy * 3 + 2] * rp[2];
                }
            }
            g_y3s[p * (NA * W) + a * 32 + u] = s;
        }
    }
}

/* --------------------- gather: patches = x_bg + lin·Δ -------------------- */
__global__ __launch_bounds__(256) void gather_kernel(const float* __restrict__ linw) {
    __shared__ float diff[NA * W];
    __shared__ int anch[60];
    int p = blockIdx.x, t = threadIdx.x;
    if (!g_nz[p]) { if (t < 25) g_patches[p * 25 + t] = g_xbg[t]; return; }
    if (t < 60) anch[t] = g_anchor[p * 60 + t];
    __syncthreads();
    for (int e = t; e < NA * W; e += 256) {
        int a = e >> 5, u = e & 31;
        diff[e] = g_y3s[p * (NA * W) + e] - g_bg3[a * 128 + anch[a] + u];
    }
    __syncthreads();
    int warp = t >> 5, lane = t & 31;
    for (int k = warp; k < 25; k += 8) {
        const float* wk = linw + k * NPIX;
        float s = 0.f;
        for (int e = lane; e < NA * W; e += 32) {
            int a = e >> 5, u = e & 31;
            s += diff[e] * __ldg(&wk[a * 128 + anch[a] + u]);
        }
        for (int o = 16; o; o >>= 1) s += __shfl_down_sync(0xffffffffu, s, o);
        if (!lane) g_patches[p * 25 + k] = g_xbg[k] + s;
    }
}

/* ---------------- recon: fill 0.5 then scatter sigmoid ------------------- */
__global__ void fill_kernel(float* __restrict__ out) {
    int i = blockIdx.x * blockDim.x + threadIdx.x;
    if (i < IMGW * IMGW) out[i] = 0.5f;
}
__global__ void scatter_kernel(const int* __restrict__ starts, float* __restrict__ out) {
    int t = blockIdx.x * blockDim.x + threadIdx.x;
    if (t >= NP * 25) return;
    int p = t / 25, q = t - p * 25;
    int i = starts[2 * p] + q / 5;
    int j = starts[2 * p + 1] + q % 5;
    float v = g_patches[t];
    out[i * IMGW + j] = 1.f / (1.f + expf(-v));
}

/* ------------------------------- radon ----------------------------------- */
__global__ __launch_bounds__(128) void radon_kernel(float* __restrict__ out) {
    int a = blockIdx.x, tid = threadIdx.x;
    double ang = (double)a * (M_PI / 180.0);
    float ct = (float)cos(ang), st = (float)sin(ang);
    float t = (float)tid - 63.5f;
    const float* img = out;
    float accum = 0.f;
    for (int ss = 0; ss < 128; ++ss) {
        float s = (float)ss - 63.5f;
        float x = 63.5f + t * ct - s * st;
        float y = 63.5f + t * st + s * ct;
        float fx = floorf(x), fy = floorf(y);
        int x0 = (int)fx, y0 = (int)fy;
        float wx = x - fx, wy = y - fy;
        float v00 = 0.f, v10 = 0.f, v01 = 0.f, v11 = 0.f;
        if (x0 >= 0 && x0 < 128 && y0 >= 0 && y0 < 128)         v00 = __ldg(&img[y0 * 128 + x0]);
        if (x0 + 1 >= 0 && x0 + 1 < 128 && y0 >= 0 && y0 < 128) v10 = __ldg(&img[y0 * 128 + x0 + 1]);
        if (x0 >= 0 && x0 < 128 && y0 + 1 >= 0 && y0 + 1 < 128) v01 = __ldg(&img[(y0 + 1) * 128 + x0]);
        if (x0 + 1 >= 0 && x0 + 1 < 128 && y0 + 1 >= 0 && y0 + 1 < 128)
            v11 = __ldg(&img[(y0 + 1) * 128 + x0 + 1]);
        accum += v00 * (1.f - wx) * (1.f - wy) + v10 * wx * (1.f - wy)
               + v01 * (1.f - wx) * wy + v11 * wx * wy;
    }
    out[IMGW * IMGW + a * 128 + tid] = accum;
}

/* ------------------------------- launch ---------------------------------- */
extern "C" void kernel_launch(void* const* d_in, const int* in_sizes, int n_in,
                              void* d_out, int out_size)
{
    const float* sino   = (const float*)d_in[0];
    const float* w1     = (const float*)d_in[1];
    const float* b1     = (const float*)d_in[2];
    const float* w2     = (const float*)d_in[3];
    const float* b2     = (const float*)d_in[4];
    const float* w3     = (const float*)d_in[5];
    const float* b3     = (const float*)d_in[6];
    const float* linw   = (const float*)d_in[7];
    const float* linb   = (const float*)d_in[8];
    const int*   masks  = (const int*)d_in[9];
    const int*   starts = (const int*)d_in[10];
    float* out = (float*)d_out;

    cudaFuncSetAttribute(conv2s_kernel, cudaFuncAttributeMaxDynamicSharedMemorySize, C2S_SMEM);
    cudaFuncSetAttribute(conv3s_kernel, cudaFuncAttributeMaxDynamicSharedMemorySize, C3S_SMEM);

    prep_w2_kernel<<<(C2C * C1C * 9 + 255) / 256, 256>>>(w2);
    prep_small_kernel<<<1, 576>>>(w2, b1, b2);
    bg3_kernel<<<60, 128>>>(w3, b3);
    xbg_kernel<<<1, 256>>>(linw, linb);
    anchors_kernel<<<NP, 64>>>(masks);
    conv1s_kernel<<<NP, 256>>>(sino, masks, w1, b1);
    conv2s_kernel<<<dim3(10, NP), 384, C2S_SMEM>>>(b2);
    conv3s_kernel<<<NP, 256, C3S_SMEM>>>(w3, b3);
    gather_kernel<<<NP, 256>>>(linw);
    fill_kernel<<<(IMGW * IMGW + 255) / 256, 256>>>(out);
    scatter_kernel<<<(NP * 25 + 255) / 256, 256>>>(starts, out);
    radon_kernel<<<NA, 128>>>(out);
}

// round 3
// speedup vs baseline: 1.7971x; 1.3554x over previous
#include <cuda_runtime.h>
#include <math.h>

#define IMGW 128
#define NA   60
#define NPIX 7680
#define NP   625
#define C1C  32
#define C2C  64
#define W    32

/* ---------------- scratch (static device memory) ------------------------- */
__device__ float g_y1s[(size_t)NP * C1C * NA * W];
__device__ float g_y2s[(size_t)NP * C2C * NA * W];
__device__ float g_y3s[NP * NA * W];
__device__ int   g_anchor[NP * NA];
__device__ int   g_nz[NP];
__device__ float g_w2p[C1C * 9 * C2C];
__device__ float g_c1[C1C];
__device__ float g_bg2c[9 * C2C];
__device__ float g_bg3[NPIX];
__device__ float g_xbg[25];
__device__ float g_patches[NP * 25];

typedef unsigned long long u64;
__device__ __forceinline__ u64 dup2(float v) {
    u64 r; asm("mov.b64 %0,{%1,%1};" : "=l"(r) : "f"(v)); return r;
}
__device__ __forceinline__ void fma2(u64 &d, u64 a, u64 b) {
    asm("fma.rn.f32x2 %0,%1,%2,%0;" : "+l"(d) : "l"(a), "l"(b));
}
__device__ __forceinline__ float2 unpk(u64 v) {
    float2 r; asm("mov.b64 {%0,%1},%2;" : "=f"(r.x), "=f"(r.y) : "l"(v)); return r;
}

/* --------- prep: w2 transpose + c1 + bg2 classes (one kernel) ------------ */
__global__ void prep_kernel(const float* __restrict__ w2,
                            const float* __restrict__ b1,
                            const float* __restrict__ b2) {
    int b = blockIdx.x, t = threadIdx.x;
    if (b < 72) {
        int i = b * 256 + t;
        int co = i / (C1C * 9);
        int r  = i - co * (C1C * 9);
        int ci = r / 9;
        int k  = r - ci * 9;
        g_w2p[(ci * 9 + k) * C2C + co] = w2[i];
        return;
    }
    __shared__ float c1s[32];
    if (t < 32) { float v = fmaxf(b1[t], 0.f); c1s[t] = v; g_c1[t] = v; }
    __syncthreads();
    for (int it = t; it < 576; it += 256) {
        int co = it & 63, cls = it >> 6;
        int ry = cls / 3, rx = cls - ry * 3;
        float s = b2[co];
        for (int ci = 0; ci < 32; ++ci) {
            float wsum = 0.f;
            for (int dy = 0; dy < 3; ++dy) {
                if (ry == 0 && dy == 0) continue;
                if (ry == 2 && dy == 2) continue;
                for (int dx = 0; dx < 3; ++dx) {
                    if (rx == 0 && dx == 0) continue;
                    if (rx == 2 && dx == 2) continue;
                    wsum += w2[co * 288 + ci * 9 + dy * 3 + dx];
                }
            }
            s += wsum * c1s[ci];
        }
        g_bg2c[cls * 64 + co] = fmaxf(s, 0.f);
    }
}

/* --------------------------- anchors + nz flag --------------------------- */
__global__ void anchors_kernel(const int* __restrict__ masks) {
    __shared__ int nzf;
    int p = blockIdx.x, t = threadIdx.x;
    if (t == 0) nzf = 0;
    __syncthreads();
    if (t < 60) {
        const int* mp = masks + p * NPIX + t * 128;
        int L = -1, R = -1;
        for (int x = 0; x < 128; x += 4) {
            int4 m = *(const int4*)(mp + x);
            if (m.x) { if (L < 0) L = x;     R = x; }
            if (m.y) { if (L < 0) L = x + 1; R = x + 1; }
            if (m.z) { if (L < 0) L = x + 2; R = x + 2; }
            if (m.w) { if (L < 0) L = x + 3; R = x + 3; }
        }
        int anc;
        if (L < 0) anc = 48;
        else {
            nzf = 1;
            int c = (L + R) >> 1;
            anc = c - 16; if (anc < 0) anc = 0; if (anc > 96) anc = 96;
        }
        g_anchor[p * 60 + t] = anc;
    }
    __syncthreads();
    if (t == 0) g_nz[p] = nzf;
}

/* ----------------------- conv1 on strips --------------------------------- */
__global__ __launch_bounds__(256) void conv1s_kernel(
    const float* __restrict__ sino, const int* __restrict__ masks,
    const float* __restrict__ w1, const float* __restrict__ b1)
{
    int p = blockIdx.x;
    if (!g_nz[p]) return;
    __shared__ float w1s[288], b1s[32];
    __shared__ int anch[60];
    int t = threadIdx.x;
    for (int i = t; i < 288; i += 256) w1s[i] = w1[i];
    if (t < 32) b1s[t] = b1[t];
    if (t < 60) anch[t] = g_anchor[p * 60 + t];
    __syncthreads();
    const int* mp = masks + p * NPIX;
    for (int e = t; e < NA * W; e += 256) {
        int a = e >> 5, u = e & 31;
        int x = anch[a] + u;
        float tap[9];
#pragma unroll
        for (int dy = 0; dy < 3; ++dy) {
            int aa = a + dy - 1;
#pragma unroll
            for (int dx = 0; dx < 3; ++dx) {
                int xx = x + dx - 1;
                float v = 0.f;
                if (aa >= 0 && aa < 60 && xx >= 0 && xx < 128) {
                    int ii = aa * 128 + xx;
                    v = sino[ii] * (float)mp[ii];
                }
                tap[dy * 3 + dx] = v;
            }
        }
        float* op = g_y1s + (size_t)p * (C1C * NA * W) + e;
        for (int ci = 0; ci < 32; ++ci) {
            float s = b1s[ci];
#pragma unroll
            for (int k = 0; k < 9; ++k) s += w1s[ci * 9 + k] * tap[k];
            op[(size_t)ci * (NA * W)] = fmaxf(s, 0.f);
        }
    }
}

/* ---------- conv2: per-patch block, 5 chunks of 12 rows, f32x2 ----------- */
/* smem: w 18432 + y1h 32*1024 + c1 32 floats + anch 60 ints */
#define C2S_SMEM ((18432 + 32768 + 32) * 4 + 60 * 4)

__global__ __launch_bounds__(384) void conv2s_kernel(const float* __restrict__ b2)
{
    int p = blockIdx.x;
    if (!g_nz[p]) return;
    extern __shared__ float sm[];
    float* s_w  = sm;                 /* 18432 */
    float* y1h  = sm + 18432;         /* 32*1024, layout [ci][16][64] */
    float* c1s  = y1h + 32768;        /* 32 */
    int*   anch = (int*)(c1s + 32);   /* 60 */
    int tid = threadIdx.x;

    for (int i = tid; i < 18432; i += 384) s_w[i] = g_w2p[i];
    if (tid < 60) anch[tid] = g_anchor[p * 60 + tid];
    if (tid >= 64 && tid < 96) c1s[tid - 64] = g_c1[tid - 64];
    __syncthreads();

    int rr   = tid >> 5;          /* 0..11 row within chunk */
    int lane = tid & 31;
    int cobase = (lane >> 2) * 8; /* 8 co per thread */
    int u0 = (lane & 3) * 8;      /* 8 x per thread */

    const float* y1p = g_y1s + (size_t)p * (C1C * NA * W);

    float bofs[8];
#pragma unroll
    for (int c = 0; c < 8; ++c) bofs[c] = __ldg(&b2[cobase + c]);

    for (int c0 = 0; c0 < 60; c0 += 12) {
        /* x-window base over rows c0-1 .. c0+12 */
        int base = 1 << 30;
        for (int r = -1; r <= 12; ++r) {
            int a = c0 + r; a = a < 0 ? 0 : (a > 59 ? 59 : a);
            base = min(base, anch[a]);
        }
        base -= 2;

        __syncthreads();
        for (int idx = tid; idx < 32768; idx += 384) {
            int r = (idx >> 6) & 15;
            if (r >= 14) continue;
            int ci = idx >> 10, x = idx & 63;
            int a = c0 - 1 + r;
            int xx = base + x;
            float v = 0.f;
            if (a >= 0 && a < 60 && xx >= 0 && xx < 128) {
                int u = xx - anch[a];
                v = (u >= 0 && u < 32) ? y1p[ci * (NA * W) + a * 32 + u] : c1s[ci];
            }
            y1h[idx] = v;
        }
        __syncthreads();

        int a = c0 + rr;
        int off = anch[a] - base;

        u64 acc[4][8];
#pragma unroll
        for (int c = 0; c < 4; ++c)
#pragma unroll
            for (int x = 0; x < 8; ++x) acc[c][x] = 0ULL;

        for (int ci = 0; ci < 32; ++ci) {
            const float* cb = y1h + (ci << 10) + (rr << 6) + off + u0 - 1;
#pragma unroll
            for (int dy = 0; dy < 3; ++dy) {
                const float* row = cb + (dy << 6);
                u64 dv[10];
#pragma unroll
                for (int k = 0; k < 10; ++k) dv[k] = dup2(row[k]);
#pragma unroll
                for (int dx = 0; dx < 3; ++dx) {
                    const u64* wp = (const u64*)(s_w + (ci * 9 + dy * 3 + dx) * 64 + cobase);
                    u64 w0 = wp[0], w1 = wp[1], w2 = wp[2], w3 = wp[3];
#pragma unroll
                    for (int xq = 0; xq < 8; ++xq) {
                        fma2(acc[0][xq], w0, dv[dx + xq]);
                        fma2(acc[1][xq], w1, dv[dx + xq]);
                        fma2(acc[2][xq], w2, dv[dx + xq]);
                        fma2(acc[3][xq], w3, dv[dx + xq]);
                    }
                }
            }
        }

        float* ob = g_y2s + ((size_t)p * C2C + cobase) * (NA * W) + a * 32 + u0;
#pragma unroll
        for (int cp = 0; cp < 4; ++cp) {
            float blo = bofs[2 * cp], bhi = bofs[2 * cp + 1];
            float lo[8], hi[8];
#pragma unroll
            for (int x = 0; x < 8; ++x) {
                float2 u = unpk(acc[cp][x]);
                lo[x] = fmaxf(u.x + blo, 0.f);
                hi[x] = fmaxf(u.y + bhi, 0.f);
            }
            float* plo = ob + (size_t)(2 * cp) * (NA * W);
            float* phi = ob + (size_t)(2 * cp + 1) * (NA * W);
            *(float4*)(plo)     = make_float4(lo[0], lo[1], lo[2], lo[3]);
            *(float4*)(plo + 4) = make_float4(lo[4], lo[5], lo[6], lo[7]);
            *(float4*)(phi)     = make_float4(hi[0], hi[1], hi[2], hi[3]);
            *(float4*)(phi + 4) = make_float4(hi[4], hi[5], hi[6], hi[7]);
        }
    }
}

/* ------------------------- y3 background field --------------------------- */
__global__ void bg3_kernel(const float* __restrict__ w3, const float* __restrict__ b3) {
    __shared__ float bg2s[576];
    int a = blockIdx.x, x = threadIdx.x;
    for (int i = x; i < 576; i += 128) bg2s[i] = g_bg2c[i];
    __syncthreads();
    float s = b3[0];
    for (int dy = 0; dy < 3; ++dy) {
        int aa = a + dy - 1; if (aa < 0 || aa >= 60) continue;
        int ry = (aa == 0) ? 0 : ((aa == 59) ? 2 : 1);
        for (int dx = 0; dx < 3; ++dx) {
            int xx = x + dx - 1; if (xx < 0 || xx >= 128) continue;
            int rx = (xx == 0) ? 0 : ((xx == 127) ? 2 : 1);
            const float* cp = bg2s + (ry * 3 + rx) * 64;
            int k = dy * 3 + dx;
            for (int ci = 0; ci < 64; ++ci) s += w3[ci * 9 + k] * cp[ci];
        }
    }
    g_bg3[a * 128 + x] = s;
}

/* ---------------------- x_bg = lin(y3_bg), 25 blocks --------------------- */
__global__ void xbg_kernel(const float* __restrict__ linw, const float* __restrict__ linb) {
    __shared__ float red[8];
    int k = blockIdx.x, t = threadIdx.x;
    const float* wk = linw + k * NPIX;
    float s = 0.f;
    for (int n = t; n < NPIX; n += 256) s += g_bg3[n] * __ldg(&wk[n]);
    for (int o = 16; o; o >>= 1) s += __shfl_down_sync(0xffffffffu, s, o);
    if (!(t & 31)) red[t >> 5] = s;
    __syncthreads();
    if (t == 0) {
        float tot = 0.f;
#pragma unroll
        for (int w = 0; w < 8; ++w) tot += red[w];
        g_xbg[k] = tot + linb[k];
    }
}

/* ----------------------- conv3 on strips --------------------------------- */
#define C3S_SMEM ((64 * 8 * 48 + 576 + 576 + 64) * 4)

__global__ __launch_bounds__(256) void conv3s_kernel(
    const float* __restrict__ w3, const float* __restrict__ b3)
{
    int p = blockIdx.x;
    if (!g_nz[p]) return;
    extern __shared__ float sm[];
    float* y2h = sm;
    float* w3s = sm + 24576;
    float* bgc = w3s + 576;
    int*  anch = (int*)(bgc + 576);
    int t = threadIdx.x;
    for (int i = t; i < 576; i += 256) { w3s[i] = w3[i]; bgc[i] = g_bg2c[i]; }
    if (t < 60) anch[t] = g_anchor[p * 60 + t];
    float b3v = __ldg(&b3[0]);
    const float* y2p = g_y2s + (size_t)p * C2C * (NA * W);

    for (int c0 = 0; c0 < 60; c0 += 6) {
        __syncthreads();
        for (int i = t; i < 64 * 8 * 48; i += 256) {
            int ci = i / 384, rem = i - ci * 384;
            int r = rem / 48, xi = rem - r * 48;
            int a = c0 - 1 + r;
            float v = 0.f;
            if (a >= 0 && a < 60) {
                int u = xi - 8;
                int x = anch[a] + u;
                if (x >= 0 && x < 128) {
                    if (u >= 0 && u < 32) v = y2p[ci * (NA * W) + a * 32 + u];
                    else {
                        int ry = (a == 0) ? 0 : ((a == 59) ? 2 : 1);
                        int rx = (x == 0) ? 0 : ((x == 127) ? 2 : 1);
                        v = bgc[(ry * 3 + rx) * 64 + ci];
                    }
                }
            }
            y2h[i] = v;
        }
        __syncthreads();
        if (t < 192) {
            int r = t >> 5, u = t & 31;
            int a = c0 + r;
            int anca = anch[a];
            float s = b3v;
#pragma unroll
            for (int dy = 0; dy < 3; ++dy) {
                int ar = a - 1 + dy;
                int du = anca - ((ar >= 0 && ar < 60) ? anch[ar] : anca);
                int bi = 8 + du + u - 1;
                if (bi < 0) bi = 0; if (bi > 45) bi = 45;
                for (int ci = 0; ci < 64; ++ci) {
                    const float* rp = y2h + (ci * 8 + r + dy) * 48 + bi;
                    s += w3s[ci * 9 + dy * 3 + 0] * rp[0]
                       + w3s[ci * 9 + dy * 3 + 1] * rp[1]
                       + w3s[ci * 9 + dy * 3 + 2] * rp[2];
                }
            }
            g_y3s[p * (NA * W) + a * 32 + u] = s;
        }
    }
}

/* --------------------- gather: patches = x_bg + lin·Δ -------------------- */
__global__ __launch_bounds__(256) void gather_kernel(const float* __restrict__ linw) {
    __shared__ float diff[NA * W];
    __shared__ int anch[60];
    int p = blockIdx.x, t = threadIdx.x;
    if (!g_nz[p]) { if (t < 25) g_patches[p * 25 + t] = g_xbg[t]; return; }
    if (t < 60) anch[t] = g_anchor[p * 60 + t];
    __syncthreads();
    for (int e = t; e < NA * W; e += 256) {
        int a = e >> 5, u = e & 31;
        diff[e] = g_y3s[p * (NA * W) + e] - g_bg3[a * 128 + anch[a] + u];
    }
    __syncthreads();
    int warp = t >> 5, lane = t & 31;
    for (int k = warp; k < 25; k += 8) {
        const float* wk = linw + k * NPIX;
        float s = 0.f;
        for (int e = lane; e < NA * W; e += 32) {
            int a = e >> 5, u = e & 31;
            s += diff[e] * __ldg(&wk[a * 128 + anch[a] + u]);
        }
        for (int o = 16; o; o >>= 1) s += __shfl_down_sync(0xffffffffu, s, o);
        if (!lane) g_patches[p * 25 + k] = g_xbg[k] + s;
    }
}

/* ------------- recon: fused fill + scatter + sigmoid --------------------- */
__global__ void recon_kernel(float* __restrict__ out) {
    int i = blockIdx.x * 256 + threadIdx.x;
    if (i >= IMGW * IMGW) return;
    int y = i >> 7, x = i & 127;
    float v = 0.5f;
    if (y < 125 && x < 125) {
        int py = y / 5, px = x / 5;
        int qy = y - py * 5, qx = x - px * 5;
        float z = g_patches[(py * 25 + px) * 25 + qy * 5 + qx];
        v = 1.f / (1.f + expf(-z));
    }
    out[i] = v;
}

/* ------------------------------- radon ----------------------------------- */
__global__ __launch_bounds__(128) void radon_kernel(float* __restrict__ out) {
    int a = blockIdx.x, tid = threadIdx.x;
    double ang = (double)a * (M_PI / 180.0);
    float ct = (float)cos(ang), st = (float)sin(ang);
    float t = (float)tid - 63.5f;
    const float* img = out;
    float accum = 0.f;
    for (int ss = 0; ss < 128; ++ss) {
        float s = (float)ss - 63.5f;
        float x = 63.5f + t * ct - s * st;
        float y = 63.5f + t * st + s * ct;
        float fx = floorf(x), fy = floorf(y);
        int x0 = (int)fx, y0 = (int)fy;
        float wx = x - fx, wy = y - fy;
        float v00 = 0.f, v10 = 0.f, v01 = 0.f, v11 = 0.f;
        if (x0 >= 0 && x0 < 128 && y0 >= 0 && y0 < 128)         v00 = __ldg(&img[y0 * 128 + x0]);
        if (x0 + 1 >= 0 && x0 + 1 < 128 && y0 >= 0 && y0 < 128) v10 = __ldg(&img[y0 * 128 + x0 + 1]);
        if (x0 >= 0 && x0 < 128 && y0 + 1 >= 0 && y0 + 1 < 128) v01 = __ldg(&img[(y0 + 1) * 128 + x0]);
        if (x0 + 1 >= 0 && x0 + 1 < 128 && y0 + 1 >= 0 && y0 + 1 < 128)
            v11 = __ldg(&img[(y0 + 1) * 128 + x0 + 1]);
        accum += v00 * (1.f - wx) * (1.f - wy) + v10 * wx * (1.f - wy)
               + v01 * (1.f - wx) * wy + v11 * wx * wy;
    }
    out[IMGW * IMGW + a * 128 + tid] = accum;
}

/* ------------------------------- launch ---------------------------------- */
extern "C" void kernel_launch(void* const* d_in, const int* in_sizes, int n_in,
                              void* d_out, int out_size)
{
    const float* sino   = (const float*)d_in[0];
    const float* w1     = (const float*)d_in[1];
    const float* b1     = (const float*)d_in[2];
    const float* w2     = (const float*)d_in[3];
    const float* b2     = (const float*)d_in[4];
    const float* w3     = (const float*)d_in[5];
    const float* b3     = (const float*)d_in[6];
    const float* linw   = (const float*)d_in[7];
    const float* linb   = (const float*)d_in[8];
    const int*   masks  = (const int*)d_in[9];
    float* out = (float*)d_out;

    cudaFuncSetAttribute(conv2s_kernel, cudaFuncAttributeMaxDynamicSharedMemorySize, C2S_SMEM);
    cudaFuncSetAttribute(conv3s_kernel, cudaFuncAttributeMaxDynamicSharedMemorySize, C3S_SMEM);

    prep_kernel<<<73, 256>>>(w2, b1, b2);          /* 0 */
    anchors_kernel<<<NP, 64>>>(masks);             /* 1 */
    conv1s_kernel<<<NP, 256>>>(sino, masks, w1, b1); /* 2 */
    conv2s_kernel<<<NP, 384, C2S_SMEM>>>(b2);      /* 3  <- profiled slot */
    bg3_kernel<<<60, 128>>>(w3, b3);               /* 4 */
    xbg_kernel<<<25, 256>>>(linw, linb);           /* 5 */
    conv3s_kernel<<<NP, 256, C3S_SMEM>>>(w3, b3);  /* 6 */
    gather_kernel<<<NP, 256>>>(linw);              /* 7 */
    recon_kernel<<<(IMGW * IMGW + 255) / 256, 256>>>(out); /* 8 */
    radon_kernel<<<NA, 128>>>(out);                /* 9 */
}

// round 4
// speedup vs baseline: 1.8756x; 1.0437x over previous
#include <cuda_runtime.h>
#include <math.h>

#define IMGW 128
#define NA   60
#define NPIX 7680
#define NP   625
#define C1C  32
#define C2C  64
#define W    32

/* ---------------- scratch (static device memory) ------------------------- */
__device__ float g_y1s[(size_t)NP * C1C * NA * W];
__device__ float g_y2s[(size_t)NP * C2C * NA * W];
__device__ float g_y3s[NP * NA * W];
__device__ int   g_anchor[NP * NA];
__device__ int   g_nz[NP];
__device__ float g_w2p[C1C * 9 * C2C];
__device__ float g_c1[C1C];
__device__ float g_bg2c[9 * C2C];
__device__ float g_bg3[NPIX];
__device__ float g_xbg[25];
__device__ float g_patches[NP * 25];

typedef unsigned long long u64;
__device__ __forceinline__ u64 dup2(float v) {
    u64 r; asm("mov.b64 %0,{%1,%1};" : "=l"(r) : "f"(v)); return r;
}
__device__ __forceinline__ void fma2(u64 &d, u64 a, u64 b) {
    asm("fma.rn.f32x2 %0,%1,%2,%0;" : "+l"(d) : "l"(a), "l"(b));
}
__device__ __forceinline__ float2 unpk(u64 v) {
    float2 r; asm("mov.b64 {%0,%1},%2;" : "=f"(r.x), "=f"(r.y) : "l"(v)); return r;
}

/* --------- prep: w2 transpose + c1 + bg2 classes (one kernel) ------------ */
__global__ void prep_kernel(const float* __restrict__ w2,
                            const float* __restrict__ b1,
                            const float* __restrict__ b2) {
    int b = blockIdx.x, t = threadIdx.x;
    if (b < 72) {
        int i = b * 256 + t;
        int co = i / (C1C * 9);
        int r  = i - co * (C1C * 9);
        int ci = r / 9;
        int k  = r - ci * 9;
        g_w2p[(ci * 9 + k) * C2C + co] = w2[i];
        return;
    }
    __shared__ float c1s[32];
    if (t < 32) { float v = fmaxf(b1[t], 0.f); c1s[t] = v; g_c1[t] = v; }
    __syncthreads();
    for (int it = t; it < 576; it += 256) {
        int co = it & 63, cls = it >> 6;
        int ry = cls / 3, rx = cls - ry * 3;
        float s = b2[co];
        for (int ci = 0; ci < 32; ++ci) {
            float wsum = 0.f;
            for (int dy = 0; dy < 3; ++dy) {
                if (ry == 0 && dy == 0) continue;
                if (ry == 2 && dy == 2) continue;
                for (int dx = 0; dx < 3; ++dx) {
                    if (rx == 0 && dx == 0) continue;
                    if (rx == 2 && dx == 2) continue;
                    wsum += w2[co * 288 + ci * 9 + dy * 3 + dx];
                }
            }
            s += wsum * c1s[ci];
        }
        g_bg2c[cls * 64 + co] = fmaxf(s, 0.f);
    }
}

/* --------------------------- anchors + nz flag --------------------------- */
__global__ void anchors_kernel(const int* __restrict__ masks) {
    __shared__ int nzf;
    int p = blockIdx.x, t = threadIdx.x;
    if (t == 0) nzf = 0;
    __syncthreads();
    if (t < 60) {
        const int* mp = masks + p * NPIX + t * 128;
        int L = -1, R = -1;
        for (int x = 0; x < 128; x += 4) {
            int4 m = *(const int4*)(mp + x);
            if (m.x) { if (L < 0) L = x;     R = x; }
            if (m.y) { if (L < 0) L = x + 1; R = x + 1; }
            if (m.z) { if (L < 0) L = x + 2; R = x + 2; }
            if (m.w) { if (L < 0) L = x + 3; R = x + 3; }
        }
        int anc;
        if (L < 0) anc = 48;
        else {
            nzf = 1;
            int c = (L + R) >> 1;
            anc = c - 16; if (anc < 0) anc = 0; if (anc > 96) anc = 96;
        }
        g_anchor[p * 60 + t] = anc;
    }
    __syncthreads();
    if (t == 0) g_nz[p] = nzf;
}

/* ----------------------- conv1 on strips (smem-staged) ------------------- */
__global__ __launch_bounds__(256) void conv1s_kernel(
    const float* __restrict__ sino, const int* __restrict__ masks,
    const float* __restrict__ w1, const float* __restrict__ b1)
{
    int p = blockIdx.x;
    if (!g_nz[p]) return;
    __shared__ float ms[NPIX];
    __shared__ float w1s[288], b1s[32];
    __shared__ int anch[60];
    int t = threadIdx.x;
    for (int i = t; i < 288; i += 256) w1s[i] = w1[i];
    if (t < 32) b1s[t] = b1[t];
    if (t < 60) anch[t] = g_anchor[p * 60 + t];
    const int* mp = masks + p * NPIX;
    for (int i = t; i < NPIX; i += 256) ms[i] = sino[i] * (float)mp[i];
    __syncthreads();

    for (int e = t; e < NA * W; e += 256) {
        int a = e >> 5, u = e & 31;
        int x = anch[a] + u;
        float tap[9];
#pragma unroll
        for (int dy = 0; dy < 3; ++dy) {
            int aa = a + dy - 1;
#pragma unroll
            for (int dx = 0; dx < 3; ++dx) {
                int xx = x + dx - 1;
                float v = 0.f;
                if (aa >= 0 && aa < 60 && xx >= 0 && xx < 128) v = ms[aa * 128 + xx];
                tap[dy * 3 + dx] = v;
            }
        }
        float* op = g_y1s + (size_t)p * (C1C * NA * W) + e;
        for (int ci = 0; ci < 32; ++ci) {
            float s = b1s[ci];
#pragma unroll
            for (int k = 0; k < 9; ++k) s += w1s[ci * 9 + k] * tap[k];
            op[(size_t)ci * (NA * W)] = fmaxf(s, 0.f);
        }
    }
}

/* ---------- conv2: co-split (2 blocks/patch), 8-row chunks, f32x2 -------- */
/* smem: w 9216 + y1h 32*10*48=15360 + c1 32 + anch 60 */
#define C2S_SMEM ((9216 + 15360 + 32) * 4 + 60 * 4)

__global__ __launch_bounds__(256, 2) void conv2s_kernel(const float* __restrict__ b2)
{
    int p = blockIdx.y;
    if (!g_nz[p]) return;
    extern __shared__ float sm[];
    float* s_w  = sm;                 /* [ci*9+k][32] */
    float* y1h  = sm + 9216;          /* [ci][10][48] */
    float* c1s  = y1h + 15360;        /* 32 */
    int*   anch = (int*)(c1s + 32);   /* 60 */
    int tid = threadIdx.x;
    int coh = blockIdx.x * 32;        /* co half base */

    for (int i = tid; i < 9216; i += 256) {
        int row = i >> 5, c = i & 31;
        s_w[i] = g_w2p[(row << 6) + coh + c];
    }
    if (tid < 60) anch[tid] = g_anchor[p * 60 + tid];
    if (tid >= 64 && tid < 96) c1s[tid - 64] = g_c1[tid - 64];
    __syncthreads();

    int rr   = tid >> 5;          /* row in chunk 0..7 */
    int lane = tid & 31;
    int cog  = (lane >> 3) * 8;   /* 8 co per thread within half */
    int u0   = (lane & 7) * 4;    /* 4 x per thread */

    const float* y1p = g_y1s + (size_t)p * (C1C * NA * W);

    float bofs[8];
#pragma unroll
    for (int c = 0; c < 8; ++c) bofs[c] = __ldg(&b2[coh + cog + c]);

    for (int c0 = 0; c0 < 60; c0 += 8) {
        int base = 1 << 30;
#pragma unroll
        for (int r = -1; r <= 8; ++r) {
            int a = c0 + r; a = a < 0 ? 0 : (a > 59 ? 59 : a);
            base = min(base, anch[a]);
        }
        base -= 2;

        __syncthreads();
        for (int idx = tid; idx < 15360; idx += 256) {
            int ci  = idx / 480;
            int rem = idx - ci * 480;
            int r   = rem / 48;
            int x   = rem - r * 48;
            int a  = c0 - 1 + r;
            int xx = base + x;
            float v = 0.f;
            if (a >= 0 && a < 60 && xx >= 0 && xx < 128) {
                int u = xx - anch[a];
                v = (u >= 0 && u < 32) ? y1p[ci * (NA * W) + a * 32 + u] : c1s[ci];
            }
            y1h[idx] = v;
        }
        __syncthreads();

        int a = c0 + rr;
        if (a >= 60) continue;
        int off = anch[a] - base;

        u64 acc[4][4];
#pragma unroll
        for (int c = 0; c < 4; ++c)
#pragma unroll
            for (int x = 0; x < 4; ++x) acc[c][x] = 0ULL;

        for (int ci = 0; ci < 32; ++ci) {
            const float* cb = y1h + ci * 480 + rr * 48 + off + u0 - 1;
#pragma unroll
            for (int dy = 0; dy < 3; ++dy) {
                const float* row = cb + dy * 48;
                u64 dv[6];
#pragma unroll
                for (int k = 0; k < 6; ++k) dv[k] = dup2(row[k]);
#pragma unroll
                for (int dx = 0; dx < 3; ++dx) {
                    const u64* wp = (const u64*)(s_w + (ci * 9 + dy * 3 + dx) * 32 + cog);
                    u64 w0 = wp[0], w1 = wp[1], w2 = wp[2], w3 = wp[3];
#pragma unroll
                    for (int xq = 0; xq < 4; ++xq) {
                        fma2(acc[0][xq], w0, dv[dx + xq]);
                        fma2(acc[1][xq], w1, dv[dx + xq]);
                        fma2(acc[2][xq], w2, dv[dx + xq]);
                        fma2(acc[3][xq], w3, dv[dx + xq]);
                    }
                }
            }
        }

        float* ob = g_y2s + ((size_t)p * C2C + coh + cog) * (NA * W) + a * 32 + u0;
#pragma unroll
        for (int cp = 0; cp < 4; ++cp) {
            float blo = bofs[2 * cp], bhi = bofs[2 * cp + 1];
            float2 v0 = unpk(acc[cp][0]), v1 = unpk(acc[cp][1]);
            float2 v2 = unpk(acc[cp][2]), v3 = unpk(acc[cp][3]);
            *(float4*)(ob + (size_t)(2 * cp) * (NA * W)) =
                make_float4(fmaxf(v0.x + blo, 0.f), fmaxf(v1.x + blo, 0.f),
                            fmaxf(v2.x + blo, 0.f), fmaxf(v3.x + blo, 0.f));
            *(float4*)(ob + (size_t)(2 * cp + 1) * (NA * W)) =
                make_float4(fmaxf(v0.y + bhi, 0.f), fmaxf(v1.y + bhi, 0.f),
                            fmaxf(v2.y + bhi, 0.f), fmaxf(v3.y + bhi, 0.f));
        }
    }
}

/* ------------------------- y3 background field --------------------------- */
__global__ void bg3_kernel(const float* __restrict__ w3, const float* __restrict__ b3) {
    __shared__ float bg2s[576];
    int a = blockIdx.x, x = threadIdx.x;
    for (int i = x; i < 576; i += 128) bg2s[i] = g_bg2c[i];
    __syncthreads();
    float s = b3[0];
    for (int dy = 0; dy < 3; ++dy) {
        int aa = a + dy - 1; if (aa < 0 || aa >= 60) continue;
        int ry = (aa == 0) ? 0 : ((aa == 59) ? 2 : 1);
        for (int dx = 0; dx < 3; ++dx) {
            int xx = x + dx - 1; if (xx < 0 || xx >= 128) continue;
            int rx = (xx == 0) ? 0 : ((xx == 127) ? 2 : 1);
            const float* cp = bg2s + (ry * 3 + rx) * 64;
            int k = dy * 3 + dx;
            for (int ci = 0; ci < 64; ++ci) s += w3[ci * 9 + k] * cp[ci];
        }
    }
    g_bg3[a * 128 + x] = s;
}

/* ---------------------- x_bg = lin(y3_bg), 25 blocks --------------------- */
__global__ void xbg_kernel(const float* __restrict__ linw, const float* __restrict__ linb) {
    __shared__ float red[8];
    int k = blockIdx.x, t = threadIdx.x;
    const float* wk = linw + k * NPIX;
    float s = 0.f;
    for (int n = t; n < NPIX; n += 256) s += g_bg3[n] * __ldg(&wk[n]);
    for (int o = 16; o; o >>= 1) s += __shfl_down_sync(0xffffffffu, s, o);
    if (!(t & 31)) red[t >> 5] = s;
    __syncthreads();
    if (t == 0) {
        float tot = 0.f;
#pragma unroll
        for (int w = 0; w < 8; ++w) tot += red[w];
        g_xbg[k] = tot + linb[k];
    }
}

/* ----------------------- conv3 on strips --------------------------------- */
#define C3S_SMEM ((64 * 8 * 48 + 576 + 576 + 64) * 4)

__global__ __launch_bounds__(256) void conv3s_kernel(
    const float* __restrict__ w3, const float* __restrict__ b3)
{
    int p = blockIdx.x;
    if (!g_nz[p]) return;
    extern __shared__ float sm[];
    float* y2h = sm;
    float* w3s = sm + 24576;
    float* bgc = w3s + 576;
    int*  anch = (int*)(bgc + 576);
    int t = threadIdx.x;
    for (int i = t; i < 576; i += 256) { w3s[i] = w3[i]; bgc[i] = g_bg2c[i]; }
    if (t < 60) anch[t] = g_anchor[p * 60 + t];
    float b3v = __ldg(&b3[0]);
    const float* y2p = g_y2s + (size_t)p * C2C * (NA * W);

    for (int c0 = 0; c0 < 60; c0 += 6) {
        __syncthreads();
        for (int i = t; i < 64 * 8 * 48; i += 256) {
            int ci = i / 384, rem = i - ci * 384;
            int r = rem / 48, xi = rem - r * 48;
            int a = c0 - 1 + r;
            float v = 0.f;
            if (a >= 0 && a < 60) {
                int u = xi - 8;
                int x = anch[a] + u;
                if (x >= 0 && x < 128) {
                    if (u >= 0 && u < 32) v = y2p[ci * (NA * W) + a * 32 + u];
                    else {
                        int ry = (a == 0) ? 0 : ((a == 59) ? 2 : 1);
                        int rx = (x == 0) ? 0 : ((x == 127) ? 2 : 1);
                        v = bgc[(ry * 3 + rx) * 64 + ci];
                    }
                }
            }
            y2h[i] = v;
        }
        __syncthreads();
        if (t < 192) {
            int r = t >> 5, u = t & 31;
            int a = c0 + r;
            int anca = anch[a];
            float s = b3v;
#pragma unroll
            for (int dy = 0; dy < 3; ++dy) {
                int ar = a - 1 + dy;
                int du = anca - ((ar >= 0 && ar < 60) ? anch[ar] : anca);
                int bi = 8 + du + u - 1;
                if (bi < 0) bi = 0; if (bi > 45) bi = 45;
                for (int ci = 0; ci < 64; ++ci) {
                    const float* rp = y2h + (ci * 8 + r + dy) * 48 + bi;
                    s += w3s[ci * 9 + dy * 3 + 0] * rp[0]
                       + w3s[ci * 9 + dy * 3 + 1] * rp[1]
                       + w3s[ci * 9 + dy * 3 + 2] * rp[2];
                }
            }
            g_y3s[p * (NA * W) + a * 32 + u] = s;
        }
    }
}

/* --------------------- gather: patches = x_bg + lin·Δ -------------------- */
__global__ __launch_bounds__(256) void gather_kernel(const float* __restrict__ linw) {
    __shared__ float diff[NA * W];
    __shared__ int anch[60];
    int p = blockIdx.x, t = threadIdx.x;
    if (!g_nz[p]) { if (t < 25) g_patches[p * 25 + t] = g_xbg[t]; return; }
    if (t < 60) anch[t] = g_anchor[p * 60 + t];
    __syncthreads();
    for (int e = t; e < NA * W; e += 256) {
        int a = e >> 5, u = e & 31;
        diff[e] = g_y3s[p * (NA * W) + e] - g_bg3[a * 128 + anch[a] + u];
    }
    __syncthreads();
    int warp = t >> 5, lane = t & 31;
    for (int k = warp; k < 25; k += 8) {
        const float* wk = linw + k * NPIX;
        float s = 0.f;
        for (int e = lane; e < NA * W; e += 32) {
            int a = e >> 5, u = e & 31;
            s += diff[e] * __ldg(&wk[a * 128 + anch[a] + u]);
        }
        for (int o = 16; o; o >>= 1) s += __shfl_down_sync(0xffffffffu, s, o);
        if (!lane) g_patches[p * 25 + k] = g_xbg[k] + s;
    }
}

/* ------------- recon: fused fill + scatter + sigmoid --------------------- */
__global__ void recon_kernel(float* __restrict__ out) {
    int i = blockIdx.x * 256 + threadIdx.x;
    if (i >= IMGW * IMGW) return;
    int y = i >> 7, x = i & 127;
    float v = 0.5f;
    if (y < 125 && x < 125) {
        int py = y / 5, px = x / 5;
        int qy = y - py * 5, qx = x - px * 5;
        float z = g_patches[(py * 25 + px) * 25 + qy * 5 + qx];
        v = 1.f / (1.f + expf(-z));
    }
    out[i] = v;
}

/* ------------------------------- radon ----------------------------------- */
__global__ __launch_bounds__(128) void radon_kernel(float* __restrict__ out) {
    int a = blockIdx.x, tid = threadIdx.x;
    double ang = (double)a * (M_PI / 180.0);
    float ct = (float)cos(ang), st = (float)sin(ang);
    float t = (float)tid - 63.5f;
    const float* img = out;
    float accum = 0.f;
    for (int ss = 0; ss < 128; ++ss) {
        float s = (float)ss - 63.5f;
        float x = 63.5f + t * ct - s * st;
        float y = 63.5f + t * st + s * ct;
        float fx = floorf(x), fy = floorf(y);
        int x0 = (int)fx, y0 = (int)fy;
        float wx = x - fx, wy = y - fy;
        float v00 = 0.f, v10 = 0.f, v01 = 0.f, v11 = 0.f;
        if (x0 >= 0 && x0 < 128 && y0 >= 0 && y0 < 128)         v00 = __ldg(&img[y0 * 128 + x0]);
        if (x0 + 1 >= 0 && x0 + 1 < 128 && y0 >= 0 && y0 < 128) v10 = __ldg(&img[y0 * 128 + x0 + 1]);
        if (x0 >= 0 && x0 < 128 && y0 + 1 >= 0 && y0 + 1 < 128) v01 = __ldg(&img[(y0 + 1) * 128 + x0]);
        if (x0 + 1 >= 0 && x0 + 1 < 128 && y0 + 1 >= 0 && y0 + 1 < 128)
            v11 = __ldg(&img[(y0 + 1) * 128 + x0 + 1]);
        accum += v00 * (1.f - wx) * (1.f - wy) + v10 * wx * (1.f - wy)
               + v01 * (1.f - wx) * wy + v11 * wx * wy;
    }
    out[IMGW * IMGW + a * 128 + tid] = accum;
}

/* ------------------------------- launch ---------------------------------- */
extern "C" void kernel_launch(void* const* d_in, const int* in_sizes, int n_in,
                              void* d_out, int out_size)
{
    const float* sino   = (const float*)d_in[0];
    const float* w1     = (const float*)d_in[1];
    const float* b1     = (const float*)d_in[2];
    const float* w2     = (const float*)d_in[3];
    const float* b2     = (const float*)d_in[4];
    const float* w3     = (const float*)d_in[5];
    const float* b3     = (const float*)d_in[6];
    const float* linw   = (const float*)d_in[7];
    const float* linb   = (const float*)d_in[8];
    const int*   masks  = (const int*)d_in[9];
    float* out = (float*)d_out;

    cudaFuncSetAttribute(conv2s_kernel, cudaFuncAttributeMaxDynamicSharedMemorySize, C2S_SMEM);
    cudaFuncSetAttribute(conv3s_kernel, cudaFuncAttributeMaxDynamicSharedMemorySize, C3S_SMEM);

    prep_kernel<<<73, 256>>>(w2, b1, b2);                   /* 0 */
    anchors_kernel<<<NP, 64>>>(masks);                      /* 1 */
    conv1s_kernel<<<NP, 256>>>(sino, masks, w1, b1);        /* 2 */
    conv2s_kernel<<<dim3(2, NP), 256, C2S_SMEM>>>(b2);      /* 3 */
    bg3_kernel<<<60, 128>>>(w3, b3);                        /* 4 */
    xbg_kernel<<<25, 256>>>(linw, linb);                    /* 5 */
    conv3s_kernel<<<NP, 256, C3S_SMEM>>>(w3, b3);           /* 6 */
    gather_kernel<<<NP, 256>>>(linw);                       /* 7 */
    recon_kernel<<<(IMGW * IMGW + 255) / 256, 256>>>(out);  /* 8 */
    radon_kernel<<<NA, 128>>>(out);                         /* 9 */
}

// round 8
// speedup vs baseline: 2.1379x; 1.1398x over previous
#include <cuda_runtime.h>
#include <math.h>

#define IMGW 128
#define NA   60
#define NPIX 7680
#define NP   625
#define C1C  32
#define C2C  64
#define W    32

/* ------------------- scratch (static device memory) ---------------------- */
__device__ float g_y1s[(size_t)NP * C1C * NA * W];   /* [p][ci][a][32] */
__device__ float g_y2s[(size_t)NP * C2C * NA * W];   /* [p][co][a][32] */
__device__ float g_y3s[NP * NA * W];                 /* [p][a][32] */
__device__ int   g_anchor[NP * NA];
__device__ int   g_nz[NP];
__device__ float g_w2p[C1C * 9 * C2C];               /* [ci*9+k][co] */
__device__ float g_c1[C1C];
__device__ float g_bg2c[9 * C2C];
__device__ float g_bg3[NPIX];
__device__ float g_xbg[25];
__device__ float g_patches[NP * 25];

typedef unsigned long long u64;
__device__ __forceinline__ u64 dup2(float v) {
    u64 r; asm("mov.b64 %0,{%1,%1};" : "=l"(r) : "f"(v)); return r;
}
__device__ __forceinline__ void fma2(u64 &d, u64 a, u64 b) {
    asm("fma.rn.f32x2 %0,%1,%2,%0;" : "+l"(d) : "l"(a), "l"(b));
}
__device__ __forceinline__ float2 unpk(u64 v) {
    float2 r; asm("mov.b64 {%0,%1},%2;" : "=f"(r.x), "=f"(r.y) : "l"(v)); return r;
}

/* -------------------------------- prep (R4) ------------------------------- */
__global__ void prep_kernel(const float* __restrict__ w2,
                            const float* __restrict__ b1,
                            const float* __restrict__ b2) {
    int b = blockIdx.x, t = threadIdx.x;
    if (b < 72) {
        int i = b * 256 + t;
        int co = i / 288, r = i - co * 288;
        int ci = r / 9, k = r - ci * 9;
        g_w2p[(ci * 9 + k) * 64 + co] = w2[i];
        return;
    }
    __shared__ float c1s[32];
    if (t < 32) { float v = fmaxf(b1[t], 0.f); c1s[t] = v; g_c1[t] = v; }
    __syncthreads();
    for (int it = t; it < 576; it += 256) {
        int co = it & 63, cls = it >> 6;
        int ry = cls / 3, rx = cls - ry * 3;
        float s = b2[co];
        for (int ci = 0; ci < 32; ++ci) {
            float wsum = 0.f;
            for (int dy = 0; dy < 3; ++dy) {
                if (ry == 0 && dy == 0) continue;
                if (ry == 2 && dy == 2) continue;
                for (int dx = 0; dx < 3; ++dx) {
                    if (rx == 0 && dx == 0) continue;
                    if (rx == 2 && dx == 2) continue;
                    wsum += w2[co * 288 + ci * 9 + dy * 3 + dx];
                }
            }
            s += wsum * c1s[ci];
        }
        g_bg2c[cls * 64 + co] = fmaxf(s, 0.f);
    }
}

/* ------------------------------ anchors (R4) ------------------------------ */
__global__ void anchors_kernel(const int* __restrict__ masks) {
    __shared__ int nzf;
    int p = blockIdx.x, t = threadIdx.x;
    if (t == 0) nzf = 0;
    __syncthreads();
    if (t < 60) {
        const int* mp = masks + p * NPIX + t * 128;
        int L = -1, R = -1;
        for (int x = 0; x < 128; x += 4) {
            int4 m = *(const int4*)(mp + x);
            if (m.x) { if (L < 0) L = x;     R = x; }
            if (m.y) { if (L < 0) L = x + 1; R = x + 1; }
            if (m.z) { if (L < 0) L = x + 2; R = x + 2; }
            if (m.w) { if (L < 0) L = x + 3; R = x + 3; }
        }
        int anc;
        if (L < 0) anc = 48;
        else {
            nzf = 1;
            int c = (L + R) >> 1;
            anc = c - 16; if (anc < 0) anc = 0; if (anc > 96) anc = 96;
        }
        g_anchor[p * 60 + t] = anc;
    }
    __syncthreads();
    if (t == 0) g_nz[p] = nzf;
}

/* ----------------- conv1 on strips (R4, smem-staged scalar) --------------- */
__global__ __launch_bounds__(256) void conv1s_kernel(
    const float* __restrict__ sino, const int* __restrict__ masks,
    const float* __restrict__ w1, const float* __restrict__ b1)
{
    int p = blockIdx.x;
    if (!g_nz[p]) return;
    __shared__ float ms[NPIX];
    __shared__ float w1s[288], b1s[32];
    __shared__ int anch[60];
    int t = threadIdx.x;
    for (int i = t; i < 288; i += 256) w1s[i] = w1[i];
    if (t < 32) b1s[t] = b1[t];
    if (t < 60) anch[t] = g_anchor[p * 60 + t];
    const int* mp = masks + p * NPIX;
    for (int i = t; i < NPIX; i += 256) ms[i] = sino[i] * (float)mp[i];
    __syncthreads();

    for (int e = t; e < NA * W; e += 256) {
        int a = e >> 5, u = e & 31;
        int x = anch[a] + u;
        float tap[9];
#pragma unroll
        for (int dy = 0; dy < 3; ++dy) {
            int aa = a + dy - 1;
#pragma unroll
            for (int dx = 0; dx < 3; ++dx) {
                int xx = x + dx - 1;
                float v = 0.f;
                if (aa >= 0 && aa < 60 && xx >= 0 && xx < 128) v = ms[aa * 128 + xx];
                tap[dy * 3 + dx] = v;
            }
        }
        float* op = g_y1s + (size_t)p * (C1C * NA * W) + e;
        for (int ci = 0; ci < 32; ++ci) {
            float s = b1s[ci];
#pragma unroll
            for (int k = 0; k < 9; ++k) s += w1s[ci * 9 + k] * tap[k];
            op[(size_t)ci * (NA * W)] = fmaxf(s, 0.f);
        }
    }
}

/* ------ conv2 (R4 body), chunk-split over blockIdx.z, f32x2 -------------- */
#define C2S_SMEM ((9216 + 15360 + 32) * 4 + 60 * 4)

__global__ __launch_bounds__(256, 2) void conv2s_kernel(const float* __restrict__ b2)
{
    int p = blockIdx.y;
    if (!g_nz[p]) return;
    extern __shared__ float sm[];
    float* s_w  = sm;                 /* [ci*9+k][32 half-co] */
    float* y1h  = sm + 9216;          /* [ci][10][48] */
    float* c1s  = y1h + 15360;        /* 32 */
    int*   anch = (int*)(c1s + 32);   /* 60 */
    int tid = threadIdx.x;
    int coh = blockIdx.x * 32;

    for (int i = tid; i < 9216; i += 256)
        s_w[i] = g_w2p[(i >> 5) * 64 + coh + (i & 31)];
    if (tid < 60) anch[tid] = g_anchor[p * 60 + tid];
    if (tid >= 64 && tid < 96) c1s[tid - 64] = g_c1[tid - 64];
    __syncthreads();

    int rr   = tid >> 5;
    int lane = tid & 31;
    int cog  = (lane >> 3) * 8;
    int u0   = (lane & 7) * 4;

    const float* y1p = g_y1s + (size_t)p * (C1C * NA * W);

    float bofs[8];
#pragma unroll
    for (int c = 0; c < 8; ++c) bofs[c] = __ldg(&b2[coh + cog + c]);

    int c0 = blockIdx.z * 8;
    {
        int base = 1 << 30;
#pragma unroll
        for (int r = -1; r <= 8; ++r) {
            int a = c0 + r; a = a < 0 ? 0 : (a > 59 ? 59 : a);
            base = min(base, anch[a]);
        }
        base -= 2;

        for (int idx = tid; idx < 15360; idx += 256) {
            int ci  = idx / 480;
            int rem = idx - ci * 480;
            int r   = rem / 48;
            int x   = rem - r * 48;
            int a  = c0 - 1 + r;
            int xx = base + x;
            float v = 0.f;
            if (a >= 0 && a < 60 && xx >= 0 && xx < 128) {
                int u = xx - anch[a];
                v = (u >= 0 && u < 32) ? y1p[ci * (NA * W) + a * 32 + u] : c1s[ci];
            }
            y1h[idx] = v;
        }
        __syncthreads();

        int a = c0 + rr;
        if (a >= 60) return;
        int off = anch[a] - base;

        u64 acc[4][4];
#pragma unroll
        for (int c = 0; c < 4; ++c)
#pragma unroll
            for (int x = 0; x < 4; ++x) acc[c][x] = 0ULL;

        for (int ci = 0; ci < 32; ++ci) {
            const float* cb = y1h + ci * 480 + rr * 48 + off + u0 - 1;
#pragma unroll
            for (int dy = 0; dy < 3; ++dy) {
                const float* row = cb + dy * 48;
                u64 dv[6];
#pragma unroll
                for (int k = 0; k < 6; ++k) dv[k] = dup2(row[k]);
#pragma unroll
                for (int dx = 0; dx < 3; ++dx) {
                    const u64* wp = (const u64*)(s_w + (ci * 9 + dy * 3 + dx) * 32 + cog);
                    u64 w0 = wp[0], w1 = wp[1], w2 = wp[2], w3 = wp[3];
#pragma unroll
                    for (int x = 0; x < 4; ++x) {
                        fma2(acc[0][x], w0, dv[dx + x]);
                        fma2(acc[1][x], w1, dv[dx + x]);
                        fma2(acc[2][x], w2, dv[dx + x]);
                        fma2(acc[3][x], w3, dv[dx + x]);
                    }
                }
            }
        }

        float* ob = g_y2s + ((size_t)p * C2C + coh + cog) * (NA * W) + a * 32 + u0;
#pragma unroll
        for (int cp = 0; cp < 4; ++cp) {
            float blo = bofs[2 * cp], bhi = bofs[2 * cp + 1];
            float2 v0 = unpk(acc[cp][0]), v1 = unpk(acc[cp][1]);
            float2 v2 = unpk(acc[cp][2]), v3 = unpk(acc[cp][3]);
            *(float4*)(ob + (size_t)(2 * cp) * (NA * W)) =
                make_float4(fmaxf(v0.x + blo, 0.f), fmaxf(v1.x + blo, 0.f),
                            fmaxf(v2.x + blo, 0.f), fmaxf(v3.x + blo, 0.f));
            *(float4*)(ob + (size_t)(2 * cp + 1) * (NA * W)) =
                make_float4(fmaxf(v0.y + bhi, 0.f), fmaxf(v1.y + bhi, 0.f),
                            fmaxf(v2.y + bhi, 0.f), fmaxf(v3.y + bhi, 0.f));
        }
    }
}

/* ------------------------- y3 background field (R4) ----------------------- */
__global__ void bg3_kernel(const float* __restrict__ w3, const float* __restrict__ b3) {
    __shared__ float bg2s[576];
    int a = blockIdx.x, x = threadIdx.x;
    for (int i = x; i < 576; i += 128) bg2s[i] = g_bg2c[i];
    __syncthreads();
    float s = b3[0];
    for (int dy = 0; dy < 3; ++dy) {
        int aa = a + dy - 1; if (aa < 0 || aa >= 60) continue;
        int ry = (aa == 0) ? 0 : ((aa == 59) ? 2 : 1);
        for (int dx = 0; dx < 3; ++dx) {
            int xx = x + dx - 1; if (xx < 0 || xx >= 128) continue;
            int rx = (xx == 0) ? 0 : ((xx == 127) ? 2 : 1);
            const float* cp = bg2s + (ry * 3 + rx) * 64;
            int k = dy * 3 + dx;
            for (int ci = 0; ci < 64; ++ci) s += w3[ci * 9 + k] * cp[ci];
        }
    }
    g_bg3[a * 128 + x] = s;
}

/* ---------------------- x_bg = lin(y3_bg), 25 blocks (R4) ----------------- */
__global__ void xbg_kernel(const float* __restrict__ linw, const float* __restrict__ linb) {
    __shared__ float red[8];
    int k = blockIdx.x, t = threadIdx.x;
    const float* wk = linw + k * NPIX;
    float s = 0.f;
    for (int n = t; n < NPIX; n += 256) s += g_bg3[n] * __ldg(&wk[n]);
    for (int o = 16; o; o >>= 1) s += __shfl_down_sync(0xffffffffu, s, o);
    if (!(t & 31)) red[t >> 5] = s;
    __syncthreads();
    if (t == 0) {
        float tot = 0.f;
#pragma unroll
        for (int w = 0; w < 8; ++w) tot += red[w];
        g_xbg[k] = tot + linb[k];
    }
}

/* ------------- conv3 (R4 body), chunk-split over blockIdx.x --------------- */
#define C3S_SMEM ((64 * 8 * 48 + 576 + 576 + 64) * 4)

__global__ __launch_bounds__(256) void conv3s_kernel(
    const float* __restrict__ w3, const float* __restrict__ b3)
{
    int p = blockIdx.y;
    if (!g_nz[p]) return;
    extern __shared__ float sm[];
    float* y2h = sm;
    float* w3s = sm + 24576;
    float* bgc = w3s + 576;
    int*  anch = (int*)(bgc + 576);
    int t = threadIdx.x;
    for (int i = t; i < 576; i += 256) { w3s[i] = w3[i]; bgc[i] = g_bg2c[i]; }
    if (t < 60) anch[t] = g_anchor[p * 60 + t];
    float b3v = __ldg(&b3[0]);
    const float* y2p = g_y2s + (size_t)p * C2C * (NA * W);

    int c0 = blockIdx.x * 6;
    {
        __syncthreads();
        for (int i = t; i < 64 * 8 * 48; i += 256) {
            int ci = i / 384, rem = i - ci * 384;
            int r = rem / 48, xi = rem - r * 48;
            int a = c0 - 1 + r;
            float v = 0.f;
            if (a >= 0 && a < 60) {
                int u = xi - 8;
                int x = anch[a] + u;
                if (x >= 0 && x < 128) {
                    if (u >= 0 && u < 32) v = y2p[ci * (NA * W) + a * 32 + u];
                    else {
                        int ry = (a == 0) ? 0 : ((a == 59) ? 2 : 1);
                        int rx = (x == 0) ? 0 : ((x == 127) ? 2 : 1);
                        v = bgc[(ry * 3 + rx) * 64 + ci];
                    }
                }
            }
            y2h[i] = v;
        }
        __syncthreads();
        if (t < 192) {
            int r = t >> 5, u = t & 31;
            int a = c0 + r;
            int anca = anch[a];
            float s = b3v;
#pragma unroll
            for (int dy = 0; dy < 3; ++dy) {
                int ar = a - 1 + dy;
                int du = anca - ((ar >= 0 && ar < 60) ? anch[ar] : anca);
                int bi = 8 + du + u - 1;
                if (bi < 0) bi = 0; if (bi > 45) bi = 45;
                for (int ci = 0; ci < 64; ++ci) {
                    const float* rp = y2h + (ci * 8 + r + dy) * 48 + bi;
                    s += w3s[ci * 9 + dy * 3 + 0] * rp[0]
                       + w3s[ci * 9 + dy * 3 + 1] * rp[1]
                       + w3s[ci * 9 + dy * 3 + 2] * rp[2];
                }
            }
            g_y3s[p * (NA * W) + a * 32 + u] = s;
        }
    }
}

/* --------------------- gather: patches = x_bg + lin·Δ (R4) ---------------- */
__global__ __launch_bounds__(256) void gather_kernel(const float* __restrict__ linw) {
    __shared__ float diff[NA * W];
    __shared__ int anch[60];
    int p = blockIdx.x, t = threadIdx.x;
    if (!g_nz[p]) { if (t < 25) g_patches[p * 25 + t] = g_xbg[t]; return; }
    if (t < 60) anch[t] = g_anchor[p * 60 + t];
    __syncthreads();
    for (int e = t; e < NA * W; e += 256) {
        int a = e >> 5, u = e & 31;
        diff[e] = g_y3s[p * (NA * W) + e] - g_bg3[a * 128 + anch[a] + u];
    }
    __syncthreads();
    int warp = t >> 5, lane = t & 31;
    for (int k = warp; k < 25; k += 8) {
        const float* wk = linw + k * NPIX;
        float s = 0.f;
        for (int e = lane; e < NA * W; e += 32) {
            int a = e >> 5, u = e & 31;
            s += diff[e] * __ldg(&wk[a * 128 + anch[a] + u]);
        }
        for (int o = 16; o; o >>= 1) s += __shfl_down_sync(0xffffffffu, s, o);
        if (!lane) g_patches[p * 25 + k] = g_xbg[k] + s;
    }
}

/* ------------- recon: fused fill + scatter + sigmoid (R4) ----------------- */
__global__ void recon_kernel(float* __restrict__ out) {
    int i = blockIdx.x * 256 + threadIdx.x;
    if (i >= IMGW * IMGW) return;
    int y = i >> 7, x = i & 127;
    float v = 0.5f;
    if (y < 125 && x < 125) {
        int py = y / 5, px = x / 5;
        int qy = y - py * 5, qx = x - px * 5;
        float z = g_patches[(py * 25 + px) * 25 + qy * 5 + qx];
        v = 1.f / (1.f + expf(-z));
    }
    out[i] = v;
}

/* ------------------------------- radon (R4) -------------------------------- */
__global__ __launch_bounds__(128) void radon_kernel(float* __restrict__ out) {
    int a = blockIdx.x, tid = threadIdx.x;
    double ang = (double)a * (M_PI / 180.0);
    float ct = (float)cos(ang), st = (float)sin(ang);
    float t = (float)tid - 63.5f;
    const float* img = out;
    float accum = 0.f;
    for (int ss = 0; ss < 128; ++ss) {
        float s = (float)ss - 63.5f;
        float x = 63.5f + t * ct - s * st;
        float y = 63.5f + t * st + s * ct;
        float fx = floorf(x), fy = floorf(y);
        int x0 = (int)fx, y0 = (int)fy;
        float wx = x - fx, wy = y - fy;
        float v00 = 0.f, v10 = 0.f, v01 = 0.f, v11 = 0.f;
        if (x0 >= 0 && x0 < 128 && y0 >= 0 && y0 < 128)         v00 = __ldg(&img[y0 * 128 + x0]);
        if (x0 + 1 >= 0 && x0 + 1 < 128 && y0 >= 0 && y0 < 128) v10 = __ldg(&img[y0 * 128 + x0 + 1]);
        if (x0 >= 0 && x0 < 128 && y0 + 1 >= 0 && y0 + 1 < 128) v01 = __ldg(&img[(y0 + 1) * 128 + x0]);
        if (x0 + 1 >= 0 && x0 + 1 < 128 && y0 + 1 >= 0 && y0 + 1 < 128)
            v11 = __ldg(&img[(y0 + 1) * 128 + x0 + 1]);
        accum += v00 * (1.f - wx) * (1.f - wy) + v10 * wx * (1.f - wy)
               + v01 * (1.f - wx) * wy + v11 * wx * wy;
    }
    out[IMGW * IMGW + a * 128 + tid] = accum;
}

/* ------------------------------- launch ------------------------------------ */
extern "C" void kernel_launch(void* const* d_in, const int* in_sizes, int n_in,
                              void* d_out, int out_size)
{
    const float* sino   = (const float*)d_in[0];
    const float* w1     = (const float*)d_in[1];
    const float* b1     = (const float*)d_in[2];
    const float* w2     = (const float*)d_in[3];
    const float* b2     = (const float*)d_in[4];
    const float* w3     = (const float*)d_in[5];
    const float* b3     = (const float*)d_in[6];
    const float* linw   = (const float*)d_in[7];
    const float* linb   = (const float*)d_in[8];
    const int*   masks  = (const int*)d_in[9];
    float* out = (float*)d_out;

    cudaFuncSetAttribute(conv2s_kernel, cudaFuncAttributeMaxDynamicSharedMemorySize, C2S_SMEM);
    cudaFuncSetAttribute(conv3s_kernel, cudaFuncAttributeMaxDynamicSharedMemorySize, C3S_SMEM);

    prep_kernel<<<73, 256>>>(w2, b1, b2);                       /* 0 */
    anchors_kernel<<<NP, 64>>>(masks);                          /* 1 */
    conv1s_kernel<<<NP, 256>>>(sino, masks, w1, b1);            /* 2 */
    conv2s_kernel<<<dim3(2, NP, 8), 256, C2S_SMEM>>>(b2);       /* 3 <- profiled */
    bg3_kernel<<<60, 128>>>(w3, b3);                            /* 4 */
    xbg_kernel<<<25, 256>>>(linw, linb);                        /* 5 */
    conv3s_kernel<<<dim3(10, NP), 256, C3S_SMEM>>>(w3, b3);     /* 6 */
    gather_kernel<<<NP, 256>>>(linw);                           /* 7 */
    recon_kernel<<<(IMGW * IMGW + 255) / 256, 256>>>(out);      /* 8 */
    radon_kernel<<<NA, 128>>>(out);                             /* 9 */
}

// round 9
// speedup vs baseline: 2.3629x; 1.1053x over previous
#include <cuda_runtime.h>
#include <math.h>

#define IMGW 128
#define NA   60
#define NPIX 7680
#define NP   625
#define C1C  32
#define C2C  64
#define W    32

/* ------------------- scratch (static device memory) ---------------------- */
__device__ float g_y1s[(size_t)NP * C1C * NA * W];   /* [p][ci][a][32] */
__device__ float g_y2s[(size_t)NP * C2C * NA * W];   /* [p][co][a][32] */
__device__ float g_y3s[NP * NA * W];                 /* [p][a][32] */
__device__ int   g_anchor[NP * NA];
__device__ int   g_nz[NP];
__device__ float g_w2p[C1C * 9 * C2C];               /* [ci*9+k][co] */
__device__ float g_c1[C1C];
__device__ float g_bg2c[9 * C2C];
__device__ float g_bg3[NPIX];
__device__ float g_xbg[25];
__device__ float g_patches[NP * 25];

typedef unsigned long long u64;
__device__ __forceinline__ u64 dup2(float v) {
    u64 r; asm("mov.b64 %0,{%1,%1};" : "=l"(r) : "f"(v)); return r;
}
__device__ __forceinline__ void fma2(u64 &d, u64 a, u64 b) {
    asm("fma.rn.f32x2 %0,%1,%2,%0;" : "+l"(d) : "l"(a), "l"(b));
}
__device__ __forceinline__ float2 unpk(u64 v) {
    float2 r; asm("mov.b64 {%0,%1},%2;" : "=f"(r.x), "=f"(r.y) : "l"(v)); return r;
}

/* -------------------------------- prep ------------------------------------ */
__global__ void prep_kernel(const float* __restrict__ w2,
                            const float* __restrict__ b1,
                            const float* __restrict__ b2) {
    int b = blockIdx.x, t = threadIdx.x;
    if (b < 72) {
        int i = b * 256 + t;
        int co = i / 288, r = i - co * 288;
        int ci = r / 9, k = r - ci * 9;
        g_w2p[(ci * 9 + k) * 64 + co] = w2[i];
        return;
    }
    __shared__ float c1s[32];
    if (t < 32) { float v = fmaxf(b1[t], 0.f); c1s[t] = v; g_c1[t] = v; }
    __syncthreads();
    for (int it = t; it < 576; it += 256) {
        int co = it & 63, cls = it >> 6;
        int ry = cls / 3, rx = cls - ry * 3;
        float s = b2[co];
        for (int ci = 0; ci < 32; ++ci) {
            float wsum = 0.f;
            for (int dy = 0; dy < 3; ++dy) {
                if (ry == 0 && dy == 0) continue;
                if (ry == 2 && dy == 2) continue;
                for (int dx = 0; dx < 3; ++dx) {
                    if (rx == 0 && dx == 0) continue;
                    if (rx == 2 && dx == 2) continue;
                    wsum += w2[co * 288 + ci * 9 + dy * 3 + dx];
                }
            }
            s += wsum * c1s[ci];
        }
        g_bg2c[cls * 64 + co] = fmaxf(s, 0.f);
    }
}

/* ------------------------------ anchors ----------------------------------- */
__global__ void anchors_kernel(const int* __restrict__ masks) {
    __shared__ int nzf;
    int p = blockIdx.x, t = threadIdx.x;
    if (t == 0) nzf = 0;
    __syncthreads();
    if (t < 60) {
        const int* mp = masks + p * NPIX + t * 128;
        int L = -1, R = -1;
        for (int x = 0; x < 128; x += 4) {
            int4 m = *(const int4*)(mp + x);
            if (m.x) { if (L < 0) L = x;     R = x; }
            if (m.y) { if (L < 0) L = x + 1; R = x + 1; }
            if (m.z) { if (L < 0) L = x + 2; R = x + 2; }
            if (m.w) { if (L < 0) L = x + 3; R = x + 3; }
        }
        int anc;
        if (L < 0) anc = 48;
        else {
            nzf = 1;
            int c = (L + R) >> 1;
            anc = c - 16; if (anc < 0) anc = 0; if (anc > 96) anc = 96;
        }
        g_anchor[p * 60 + t] = anc;
    }
    __syncthreads();
    if (t == 0) g_nz[p] = nzf;
}

/* ----------------- conv1 on strips (smem-staged scalar) -------------------- */
__global__ __launch_bounds__(256) void conv1s_kernel(
    const float* __restrict__ sino, const int* __restrict__ masks,
    const float* __restrict__ w1, const float* __restrict__ b1)
{
    int p = blockIdx.x;
    if (!g_nz[p]) return;
    __shared__ float ms[NPIX];
    __shared__ float w1s[288], b1s[32];
    __shared__ int anch[60];
    int t = threadIdx.x;
    for (int i = t; i < 288; i += 256) w1s[i] = w1[i];
    if (t < 32) b1s[t] = b1[t];
    if (t < 60) anch[t] = g_anchor[p * 60 + t];
    const int* mp = masks + p * NPIX;
    for (int i = t; i < NPIX; i += 256) ms[i] = sino[i] * (float)mp[i];
    __syncthreads();

    for (int e = t; e < NA * W; e += 256) {
        int a = e >> 5, u = e & 31;
        int x = anch[a] + u;
        float tap[9];
#pragma unroll
        for (int dy = 0; dy < 3; ++dy) {
            int aa = a + dy - 1;
#pragma unroll
            for (int dx = 0; dx < 3; ++dx) {
                int xx = x + dx - 1;
                float v = 0.f;
                if (aa >= 0 && aa < 60 && xx >= 0 && xx < 128) v = ms[aa * 128 + xx];
                tap[dy * 3 + dx] = v;
            }
        }
        float* op = g_y1s + (size_t)p * (C1C * NA * W) + e;
        for (int ci = 0; ci < 32; ++ci) {
            float s = b1s[ci];
#pragma unroll
            for (int k = 0; k < 9; ++k) s += w1s[ci * 9 + k] * tap[k];
            op[(size_t)ci * (NA * W)] = fmaxf(s, 0.f);
        }
    }
}

/* ------ conv2: chunk-split, division-free staging, padded smem, f32x2 ----- */
/* y1h stride per ci = 484 (10 rows x 48 + 4 pad) */
#define C2S_SMEM ((9216 + 32 * 484 + 32) * 4 + 60 * 4)

__global__ __launch_bounds__(256, 2) void conv2s_kernel(const float* __restrict__ b2)
{
    int p = blockIdx.y;
    if (!g_nz[p]) return;
    extern __shared__ float sm[];
    float* s_w  = sm;                 /* [ci*9+k][32 half-co] */
    float* y1h  = sm + 9216;          /* [ci][10*48 +pad4]   */
    float* c1s  = y1h + 32 * 484;     /* 32 */
    int*   anch = (int*)(c1s + 32);   /* 60 */
    int tid = threadIdx.x;
    int coh = blockIdx.x * 32;

    for (int i = tid; i < 9216; i += 256)
        s_w[i] = g_w2p[(i >> 5) * 64 + coh + (i & 31)];
    if (tid < 60) anch[tid] = g_anchor[p * 60 + tid];
    if (tid >= 64 && tid < 96) c1s[tid - 64] = g_c1[tid - 64];
    __syncthreads();

    int rr   = tid >> 5;
    int lane = tid & 31;
    int cog  = (lane >> 3) * 8;
    int u0   = (lane & 7) * 4;

    const float* y1p = g_y1s + (size_t)p * (C1C * NA * W);

    float bofs[8];
#pragma unroll
    for (int c = 0; c < 8; ++c) bofs[c] = __ldg(&b2[coh + cog + c]);

    int c0 = blockIdx.z * 8;
    {
        int base = 1 << 30;
#pragma unroll
        for (int r = -1; r <= 8; ++r) {
            int a = c0 + r; a = a < 0 ? 0 : (a > 59 ? 59 : a);
            base = min(base, anch[a]);
        }
        base -= 2;

        /* division-free staging: 8 threads per ci */
        {
            int ciS = tid >> 3, tq = tid & 7;
            const float* srcci = y1p + (size_t)ciS * (NA * W);
            float c1v = c1s[ciS];
            float* dstci = y1h + ciS * 484;
#pragma unroll
            for (int r = 0; r < 10; ++r) {
                int a = c0 - 1 + r;
                bool rowok = (a >= 0) && (a < 60);
                int anA = rowok ? anch[a] : 0;
                const float* rowsrc = srcci + a * 32;
                float* rowdst = dstci + r * 48;
#pragma unroll
                for (int x = tq; x < 48; x += 8) {
                    int xx = base + x;
                    int u = xx - anA;
                    float v = 0.f;
                    if (rowok && xx >= 0 && xx < 128)
                        v = (u >= 0 && u < 32) ? rowsrc[u] : c1v;
                    rowdst[x] = v;
                }
            }
        }
        __syncthreads();

        int a = c0 + rr;
        if (a >= 60) return;
        int off = anch[a] - base;

        u64 acc[4][4];
#pragma unroll
        for (int c = 0; c < 4; ++c)
#pragma unroll
            for (int x = 0; x < 4; ++x) acc[c][x] = 0ULL;

        for (int ci = 0; ci < 32; ++ci) {
            const float* cb = y1h + ci * 484 + rr * 48 + off + u0 - 1;
#pragma unroll
            for (int dy = 0; dy < 3; ++dy) {
                const float* row = cb + dy * 48;
                u64 dv[6];
#pragma unroll
                for (int k = 0; k < 6; ++k) dv[k] = dup2(row[k]);
#pragma unroll
                for (int dx = 0; dx < 3; ++dx) {
                    const u64* wp = (const u64*)(s_w + (ci * 9 + dy * 3 + dx) * 32 + cog);
                    u64 w0 = wp[0], w1 = wp[1], w2 = wp[2], w3 = wp[3];
#pragma unroll
                    for (int x = 0; x < 4; ++x) {
                        fma2(acc[0][x], w0, dv[dx + x]);
                        fma2(acc[1][x], w1, dv[dx + x]);
                        fma2(acc[2][x], w2, dv[dx + x]);
                        fma2(acc[3][x], w3, dv[dx + x]);
                    }
                }
            }
        }

        float* ob = g_y2s + ((size_t)p * C2C + coh + cog) * (NA * W) + a * 32 + u0;
#pragma unroll
        for (int cp = 0; cp < 4; ++cp) {
            float blo = bofs[2 * cp], bhi = bofs[2 * cp + 1];
            float2 v0 = unpk(acc[cp][0]), v1 = unpk(acc[cp][1]);
            float2 v2 = unpk(acc[cp][2]), v3 = unpk(acc[cp][3]);
            *(float4*)(ob + (size_t)(2 * cp) * (NA * W)) =
                make_float4(fmaxf(v0.x + blo, 0.f), fmaxf(v1.x + blo, 0.f),
                            fmaxf(v2.x + blo, 0.f), fmaxf(v3.x + blo, 0.f));
            *(float4*)(ob + (size_t)(2 * cp + 1) * (NA * W)) =
                make_float4(fmaxf(v0.y + bhi, 0.f), fmaxf(v1.y + bhi, 0.f),
                            fmaxf(v2.y + bhi, 0.f), fmaxf(v3.y + bhi, 0.f));
        }
    }
}

/* ------------------------- y3 background field ----------------------------- */
__global__ void bg3_kernel(const float* __restrict__ w3, const float* __restrict__ b3) {
    __shared__ float bg2s[576];
    int a = blockIdx.x, x = threadIdx.x;
    for (int i = x; i < 576; i += 128) bg2s[i] = g_bg2c[i];
    __syncthreads();
    float s = b3[0];
    for (int dy = 0; dy < 3; ++dy) {
        int aa = a + dy - 1; if (aa < 0 || aa >= 60) continue;
        int ry = (aa == 0) ? 0 : ((aa == 59) ? 2 : 1);
        for (int dx = 0; dx < 3; ++dx) {
            int xx = x + dx - 1; if (xx < 0 || xx >= 128) continue;
            int rx = (xx == 0) ? 0 : ((xx == 127) ? 2 : 1);
            const float* cp = bg2s + (ry * 3 + rx) * 64;
            int k = dy * 3 + dx;
            for (int ci = 0; ci < 64; ++ci) s += w3[ci * 9 + k] * cp[ci];
        }
    }
    g_bg3[a * 128 + x] = s;
}

/* ---------------------- x_bg = lin(y3_bg), 25 blocks ----------------------- */
__global__ void xbg_kernel(const float* __restrict__ linw, const float* __restrict__ linb) {
    __shared__ float red[8];
    int k = blockIdx.x, t = threadIdx.x;
    const float* wk = linw + k * NPIX;
    float s = 0.f;
    for (int n = t; n < NPIX; n += 256) s += g_bg3[n] * __ldg(&wk[n]);
    for (int o = 16; o; o >>= 1) s += __shfl_down_sync(0xffffffffu, s, o);
    if (!(t & 31)) red[t >> 5] = s;
    __syncthreads();
    if (t == 0) {
        float tot = 0.f;
#pragma unroll
        for (int w = 0; w < 8; ++w) tot += red[w];
        g_xbg[k] = tot + linb[k];
    }
}

/* ---- conv3: chunk-split, division-free staging, padded smem -------------- */
/* y2h stride per ci = 388 (8 rows x 48 + 4 pad) */
#define C3S_SMEM ((64 * 388 + 576 + 576) * 4 + 64 * 4)

__global__ __launch_bounds__(256) void conv3s_kernel(
    const float* __restrict__ w3, const float* __restrict__ b3)
{
    int p = blockIdx.y;
    if (!g_nz[p]) return;
    extern __shared__ float sm[];
    float* y2h = sm;                   /* [ci][8*48 +pad4] */
    float* w3s = sm + 64 * 388;
    float* bgc = w3s + 576;
    int*  anch = (int*)(bgc + 576);
    int t = threadIdx.x;
    for (int i = t; i < 576; i += 256) { w3s[i] = w3[i]; bgc[i] = g_bg2c[i]; }
    if (t < 60) anch[t] = g_anchor[p * 60 + t];
    float b3v = __ldg(&b3[0]);
    const float* y2p = g_y2s + (size_t)p * C2C * (NA * W);

    int c0 = blockIdx.x * 6;
    {
        __syncthreads();
        /* division-free staging: 4 threads per ci */
        {
            int ciS = t >> 2, tq = t & 3;
            const float* srcci = y2p + (size_t)ciS * (NA * W);
            float* dstci = y2h + ciS * 388;
#pragma unroll
            for (int r = 0; r < 8; ++r) {
                int a = c0 - 1 + r;
                bool rowok = (a >= 0) && (a < 60);
                int anA = rowok ? anch[a] : 0;
                int ry = (a == 0) ? 0 : ((a == 59) ? 2 : 1);
                const float* rowsrc = srcci + a * 32;
                float* rowdst = dstci + r * 48;
#pragma unroll
                for (int xi = tq; xi < 48; xi += 4) {
                    float v = 0.f;
                    if (rowok) {
                        int u = xi - 8;
                        int x = anA + u;
                        if (x >= 0 && x < 128) {
                            if (u >= 0 && u < 32) v = rowsrc[u];
                            else {
                                int rx = (x == 0) ? 0 : ((x == 127) ? 2 : 1);
                                v = bgc[(ry * 3 + rx) * 64 + ciS];
                            }
                        }
                    }
                    rowdst[xi] = v;
                }
            }
        }
        __syncthreads();
        if (t < 192) {
            int r = t >> 5, u = t & 31;
            int a = c0 + r;
            int anca = anch[a];
            float s = b3v;
#pragma unroll
            for (int dy = 0; dy < 3; ++dy) {
                int ar = a - 1 + dy;
                int du = anca - ((ar >= 0 && ar < 60) ? anch[ar] : anca);
                int bi = 8 + du + u - 1;
                if (bi < 0) bi = 0; if (bi > 45) bi = 45;
                for (int ci = 0; ci < 64; ++ci) {
                    const float* rp = y2h + ci * 388 + (r + dy) * 48 + bi;
                    s += w3s[ci * 9 + dy * 3 + 0] * rp[0]
                       + w3s[ci * 9 + dy * 3 + 1] * rp[1]
                       + w3s[ci * 9 + dy * 3 + 2] * rp[2];
                }
            }
            g_y3s[p * (NA * W) + a * 32 + u] = s;
        }
    }
}

/* --------------------- gather: patches = x_bg + lin·Δ ---------------------- */
__global__ __launch_bounds__(256) void gather_kernel(const float* __restrict__ linw) {
    __shared__ float diff[NA * W];
    __shared__ int anch[60];
    int p = blockIdx.x, t = threadIdx.x;
    if (!g_nz[p]) { if (t < 25) g_patches[p * 25 + t] = g_xbg[t]; return; }
    if (t < 60) anch[t] = g_anchor[p * 60 + t];
    __syncthreads();
    for (int e = t; e < NA * W; e += 256) {
        int a = e >> 5, u = e & 31;
        diff[e] = g_y3s[p * (NA * W) + e] - g_bg3[a * 128 + anch[a] + u];
    }
    __syncthreads();
    int warp = t >> 5, lane = t & 31;
    for (int k = warp; k < 25; k += 8) {
        const float* wk = linw + k * NPIX;
        float s = 0.f;
        for (int e = lane; e < NA * W; e += 32) {
            int a = e >> 5, u = e & 31;
            s += diff[e] * __ldg(&wk[a * 128 + anch[a] + u]);
        }
        for (int o = 16; o; o >>= 1) s += __shfl_down_sync(0xffffffffu, s, o);
        if (!lane) g_patches[p * 25 + k] = g_xbg[k] + s;
    }
}

/* ------------- recon: fused fill + scatter + sigmoid ----------------------- */
__global__ void recon_kernel(float* __restrict__ out) {
    int i = blockIdx.x * 256 + threadIdx.x;
    if (i >= IMGW * IMGW) return;
    int y = i >> 7, x = i & 127;
    float v = 0.5f;
    if (y < 125 && x < 125) {
        int py = y / 5, px = x / 5;
        int qy = y - py * 5, qx = x - px * 5;
        float z = g_patches[(py * 25 + px) * 25 + qy * 5 + qx];
        v = 1.f / (1.f + expf(-z));
    }
    out[i] = v;
}

/* ------------------------------- radon ------------------------------------- */
__global__ __launch_bounds__(128) void radon_kernel(float* __restrict__ out) {
    int a = blockIdx.x, tid = threadIdx.x;
    double ang = (double)a * (M_PI / 180.0);
    float ct = (float)cos(ang), st = (float)sin(ang);
    float t = (float)tid - 63.5f;
    const float* img = out;
    float accum = 0.f;
    for (int ss = 0; ss < 128; ++ss) {
        float s = (float)ss - 63.5f;
        float x = 63.5f + t * ct - s * st;
        float y = 63.5f + t * st + s * ct;
        float fx = floorf(x), fy = floorf(y);
        int x0 = (int)fx, y0 = (int)fy;
        float wx = x - fx, wy = y - fy;
        float v00 = 0.f, v10 = 0.f, v01 = 0.f, v11 = 0.f;
        if (x0 >= 0 && x0 < 128 && y0 >= 0 && y0 < 128)         v00 = __ldg(&img[y0 * 128 + x0]);
        if (x0 + 1 >= 0 && x0 + 1 < 128 && y0 >= 0 && y0 < 128) v10 = __ldg(&img[y0 * 128 + x0 + 1]);
        if (x0 >= 0 && x0 < 128 && y0 + 1 >= 0 && y0 + 1 < 128) v01 = __ldg(&img[(y0 + 1) * 128 + x0]);
        if (x0 + 1 >= 0 && x0 + 1 < 128 && y0 + 1 >= 0 && y0 + 1 < 128)
            v11 = __ldg(&img[(y0 + 1) * 128 + x0 + 1]);
        accum += v00 * (1.f - wx) * (1.f - wy) + v10 * wx * (1.f - wy)
               + v01 * (1.f - wx) * wy + v11 * wx * wy;
    }
    out[IMGW * IMGW + a * 128 + tid] = accum;
}

/* ------------------------------- launch ------------------------------------ */
extern "C" void kernel_launch(void* const* d_in, const int* in_sizes, int n_in,
                              void* d_out, int out_size)
{
    const float* sino   = (const float*)d_in[0];
    const float* w1     = (const float*)d_in[1];
    const float* b1     = (const float*)d_in[2];
    const float* w2     = (const float*)d_in[3];
    const float* b2     = (const float*)d_in[4];
    const float* w3     = (const float*)d_in[5];
    const float* b3     = (const float*)d_in[6];
    const float* linw   = (const float*)d_in[7];
    const float* linb   = (const float*)d_in[8];
    const int*   masks  = (const int*)d_in[9];
    float* out = (float*)d_out;

    cudaFuncSetAttribute(conv2s_kernel, cudaFuncAttributeMaxDynamicSharedMemorySize, C2S_SMEM);
    cudaFuncSetAttribute(conv3s_kernel, cudaFuncAttributeMaxDynamicSharedMemorySize, C3S_SMEM);

    prep_kernel<<<73, 256>>>(w2, b1, b2);                       /* 0 */
    anchors_kernel<<<NP, 64>>>(masks);                          /* 1 */
    conv1s_kernel<<<NP, 256>>>(sino, masks, w1, b1);            /* 2 */
    conv2s_kernel<<<dim3(2, NP, 8), 256, C2S_SMEM>>>(b2);       /* 3 <- profiled */
    bg3_kernel<<<60, 128>>>(w3, b3);                            /* 4 */
    xbg_kernel<<<25, 256>>>(linw, linb);                        /* 5 */
    conv3s_kernel<<<dim3(10, NP), 256, C3S_SMEM>>>(w3, b3);     /* 6 */
    gather_kernel<<<NP, 256>>>(linw);                           /* 7 */
    recon_kernel<<<(IMGW * IMGW + 255) / 256, 256>>>(out);      /* 8 */
    radon_kernel<<<NA, 128>>>(out);                             /* 9 */
}

// round 10
// speedup vs baseline: 3.1497x; 1.3330x over previous
#include <cuda_runtime.h>
#include <math.h>

#define IMGW 128
#define NA   60
#define NPIX 7680
#define NP   625
#define C1C  32
#define C2C  64
#define W    32

/* ------------------- scratch (static device memory) ---------------------- */
__device__ float g_y1s[(size_t)NP * C1C * NA * W];   /* [p][ci][a][32] */
__device__ float g_y2s[(size_t)NP * C2C * NA * W];   /* [p][co][a][32] */
__device__ float g_y3s[NP * NA * W];                 /* [p][a][32] */
__device__ int   g_anchor[NP * NA];
__device__ int   g_nz[NP];
__device__ float g_w2p[C1C * 9 * C2C];               /* [ci*9+k][co] */
__device__ float g_c1[C1C];
__device__ float g_bg2c[9 * C2C];
__device__ float g_bg3[NPIX];
__device__ float g_xbg[25];
__device__ float g_patches[NP * 25];

typedef unsigned long long u64;
__device__ __forceinline__ u64 dup2(float v) {
    u64 r; asm("mov.b64 %0,{%1,%1};" : "=l"(r) : "f"(v)); return r;
}
__device__ __forceinline__ void fma2(u64 &d, u64 a, u64 b) {
    asm("fma.rn.f32x2 %0,%1,%2,%0;" : "+l"(d) : "l"(a), "l"(b));
}
__device__ __forceinline__ float2 unpk(u64 v) {
    float2 r; asm("mov.b64 {%0,%1},%2;" : "=f"(r.x), "=f"(r.y) : "l"(v)); return r;
}

/* -------------------------------- prep ------------------------------------ */
__global__ void prep_kernel(const float* __restrict__ w2,
                            const float* __restrict__ b1,
                            const float* __restrict__ b2) {
    int b = blockIdx.x, t = threadIdx.x;
    if (b < 72) {
        int i = b * 256 + t;
        int co = i / 288, r = i - co * 288;
        int ci = r / 9, k = r - ci * 9;
        g_w2p[(ci * 9 + k) * 64 + co] = w2[i];
        return;
    }
    __shared__ float c1s[32];
    if (t < 32) { float v = fmaxf(b1[t], 0.f); c1s[t] = v; g_c1[t] = v; }
    __syncthreads();
    for (int it = t; it < 576; it += 256) {
        int co = it & 63, cls = it >> 6;
        int ry = cls / 3, rx = cls - ry * 3;
        float s = b2[co];
        for (int ci = 0; ci < 32; ++ci) {
            float wsum = 0.f;
            for (int dy = 0; dy < 3; ++dy) {
                if (ry == 0 && dy == 0) continue;
                if (ry == 2 && dy == 2) continue;
                for (int dx = 0; dx < 3; ++dx) {
                    if (rx == 0 && dx == 0) continue;
                    if (rx == 2 && dx == 2) continue;
                    wsum += w2[co * 288 + ci * 9 + dy * 3 + dx];
                }
            }
            s += wsum * c1s[ci];
        }
        g_bg2c[cls * 64 + co] = fmaxf(s, 0.f);
    }
}

/* ------------------------------ anchors ----------------------------------- */
__global__ void anchors_kernel(const int* __restrict__ masks) {
    __shared__ int nzf;
    int p = blockIdx.x, t = threadIdx.x;
    if (t == 0) nzf = 0;
    __syncthreads();
    if (t < 60) {
        const int* mp = masks + p * NPIX + t * 128;
        int L = -1, R = -1;
        for (int x = 0; x < 128; x += 4) {
            int4 m = *(const int4*)(mp + x);
            if (m.x) { if (L < 0) L = x;     R = x; }
            if (m.y) { if (L < 0) L = x + 1; R = x + 1; }
            if (m.z) { if (L < 0) L = x + 2; R = x + 2; }
            if (m.w) { if (L < 0) L = x + 3; R = x + 3; }
        }
        int anc;
        if (L < 0) anc = 48;
        else {
            nzf = 1;
            int c = (L + R) >> 1;
            anc = c - 16; if (anc < 0) anc = 0; if (anc > 96) anc = 96;
        }
        g_anchor[p * 60 + t] = anc;
    }
    __syncthreads();
    if (t == 0) g_nz[p] = nzf;
}

/* ----------------- conv1 on strips (smem-staged scalar) -------------------- */
__global__ __launch_bounds__(256) void conv1s_kernel(
    const float* __restrict__ sino, const int* __restrict__ masks,
    const float* __restrict__ w1, const float* __restrict__ b1)
{
    int p = blockIdx.x;
    if (!g_nz[p]) return;
    __shared__ float ms[NPIX];
    __shared__ float w1s[288], b1s[32];
    __shared__ int anch[60];
    int t = threadIdx.x;
    for (int i = t; i < 288; i += 256) w1s[i] = w1[i];
    if (t < 32) b1s[t] = b1[t];
    if (t < 60) anch[t] = g_anchor[p * 60 + t];
    const int* mp = masks + p * NPIX;
    for (int i = t; i < NPIX; i += 256) ms[i] = sino[i] * (float)mp[i];
    __syncthreads();

    for (int e = t; e < NA * W; e += 256) {
        int a = e >> 5, u = e & 31;
        int x = anch[a] + u;
        float tap[9];
#pragma unroll
        for (int dy = 0; dy < 3; ++dy) {
            int aa = a + dy - 1;
#pragma unroll
            for (int dx = 0; dx < 3; ++dx) {
                int xx = x + dx - 1;
                float v = 0.f;
                if (aa >= 0 && aa < 60 && xx >= 0 && xx < 128) v = ms[aa * 128 + xx];
                tap[dy * 3 + dx] = v;
            }
        }
        float* op = g_y1s + (size_t)p * (C1C * NA * W) + e;
        for (int ci = 0; ci < 32; ++ci) {
            float s = b1s[ci];
#pragma unroll
            for (int k = 0; k < 9; ++k) s += w1s[ci * 9 + k] * tap[k];
            op[(size_t)ci * (NA * W)] = fmaxf(s, 0.f);
        }
    }
}

/* -- conv2: co-split x4, 6-row chunks, 192 thr, 3 CTAs/SM, f32x2 ----------- */
/* s_w 4608 + y1h 32*388 = 12416 + c1 32 floats + 60 ints = ~66.9 KB */
#define C2S_SMEM ((4608 + 32 * 388 + 32) * 4 + 60 * 4)

__global__ __launch_bounds__(192, 3) void conv2s_kernel(const float* __restrict__ b2)
{
    int p = blockIdx.y;
    if (!g_nz[p]) return;
    extern __shared__ float sm[];
    float* s_w  = sm;                 /* [ci*9+k][16 co-quarter] */
    float* y1h  = sm + 4608;          /* [ci][8*48 +pad4]        */
    float* c1s  = y1h + 32 * 388;     /* 32 */
    int*   anch = (int*)(c1s + 32);   /* 60 */
    int tid = threadIdx.x;
    int coh = blockIdx.x * 16;

    for (int i = tid; i < 4608; i += 192)
        s_w[i] = g_w2p[(i >> 4) * 64 + coh + (i & 15)];
    if (tid < 60) anch[tid] = g_anchor[p * 60 + tid];
    if (tid >= 64 && tid < 96) c1s[tid - 64] = g_c1[tid - 64];
    __syncthreads();

    int rr   = tid >> 5;          /* 0..5 row within chunk */
    int lane = tid & 31;
    int cog  = (lane >> 3) * 4;   /* 4 co within quarter */
    int u0   = (lane & 7) * 4;    /* 4 x */

    const float* y1p = g_y1s + (size_t)p * (C1C * NA * W);

    float bofs[4];
#pragma unroll
    for (int c = 0; c < 4; ++c) bofs[c] = __ldg(&b2[coh + cog + c]);

    int c0 = blockIdx.z * 6;
    {
        int base = 1 << 30;
#pragma unroll
        for (int r = -1; r <= 6; ++r) {
            int a = c0 + r; a = a < 0 ? 0 : (a > 59 ? 59 : a);
            base = min(base, anch[a]);
        }
        base -= 2;

        /* division-free staging: 6 threads per ci (one div at setup) */
        {
            int ciS = tid / 6, tq = tid - ciS * 6;
            const float* srcci = y1p + (size_t)ciS * (NA * W);
            float c1v = c1s[ciS];
            float* dstci = y1h + ciS * 388;
#pragma unroll
            for (int r = 0; r < 8; ++r) {
                int a = c0 - 1 + r;
                bool rowok = (a >= 0) && (a < 60);
                int anA = rowok ? anch[a] : 0;
                const float* rowsrc = srcci + a * 32;
                float* rowdst = dstci + r * 48;
#pragma unroll
                for (int x = tq; x < 48; x += 6) {
                    int xx = base + x;
                    int u = xx - anA;
                    float v = 0.f;
                    if (rowok && xx >= 0 && xx < 128)
                        v = (u >= 0 && u < 32) ? rowsrc[u] : c1v;
                    rowdst[x] = v;
                }
            }
        }
        __syncthreads();

        int a = c0 + rr;
        int off = anch[a] - base;

        u64 acc[2][4];
#pragma unroll
        for (int c = 0; c < 2; ++c)
#pragma unroll
            for (int x = 0; x < 4; ++x) acc[c][x] = 0ULL;

        for (int ci = 0; ci < 32; ++ci) {
            const float* cb = y1h + ci * 388 + rr * 48 + off + u0 - 1;
#pragma unroll
            for (int dy = 0; dy < 3; ++dy) {
                const float* row = cb + dy * 48;
                u64 dv[6];
#pragma unroll
                for (int k = 0; k < 6; ++k) dv[k] = dup2(row[k]);
#pragma unroll
                for (int dx = 0; dx < 3; ++dx) {
                    const u64* wp = (const u64*)(s_w + (ci * 9 + dy * 3 + dx) * 16 + cog);
                    u64 w0 = wp[0], w1 = wp[1];
#pragma unroll
                    for (int x = 0; x < 4; ++x) {
                        fma2(acc[0][x], w0, dv[dx + x]);
                        fma2(acc[1][x], w1, dv[dx + x]);
                    }
                }
            }
        }

        float* ob = g_y2s + ((size_t)p * C2C + coh + cog) * (NA * W) + a * 32 + u0;
#pragma unroll
        for (int cp = 0; cp < 2; ++cp) {
            float blo = bofs[2 * cp], bhi = bofs[2 * cp + 1];
            float2 v0 = unpk(acc[cp][0]), v1 = unpk(acc[cp][1]);
            float2 v2 = unpk(acc[cp][2]), v3 = unpk(acc[cp][3]);
            *(float4*)(ob + (size_t)(2 * cp) * (NA * W)) =
                make_float4(fmaxf(v0.x + blo, 0.f), fmaxf(v1.x + blo, 0.f),
                            fmaxf(v2.x + blo, 0.f), fmaxf(v3.x + blo, 0.f));
            *(float4*)(ob + (size_t)(2 * cp + 1) * (NA * W)) =
                make_float4(fmaxf(v0.y + bhi, 0.f), fmaxf(v1.y + bhi, 0.f),
                            fmaxf(v2.y + bhi, 0.f), fmaxf(v3.y + bhi, 0.f));
        }
    }
}

/* ------------------------- y3 background field ----------------------------- */
__global__ void bg3_kernel(const float* __restrict__ w3, const float* __restrict__ b3) {
    __shared__ float bg2s[576];
    int a = blockIdx.x, x = threadIdx.x;
    for (int i = x; i < 576; i += 128) bg2s[i] = g_bg2c[i];
    __syncthreads();
    float s = b3[0];
    for (int dy = 0; dy < 3; ++dy) {
        int aa = a + dy - 1; if (aa < 0 || aa >= 60) continue;
        int ry = (aa == 0) ? 0 : ((aa == 59) ? 2 : 1);
        for (int dx = 0; dx < 3; ++dx) {
            int xx = x + dx - 1; if (xx < 0 || xx >= 128) continue;
            int rx = (xx == 0) ? 0 : ((xx == 127) ? 2 : 1);
            const float* cp = bg2s + (ry * 3 + rx) * 64;
            int k = dy * 3 + dx;
            for (int ci = 0; ci < 64; ++ci) s += w3[ci * 9 + k] * cp[ci];
        }
    }
    g_bg3[a * 128 + x] = s;
}

/* ---------------------- x_bg = lin(y3_bg), 25 blocks ----------------------- */
__global__ void xbg_kernel(const float* __restrict__ linw, const float* __restrict__ linb) {
    __shared__ float red[8];
    int k = blockIdx.x, t = threadIdx.x;
    const float* wk = linw + k * NPIX;
    float s = 0.f;
    for (int n = t; n < NPIX; n += 256) s += g_bg3[n] * __ldg(&wk[n]);
    for (int o = 16; o; o >>= 1) s += __shfl_down_sync(0xffffffffu, s, o);
    if (!(t & 31)) red[t >> 5] = s;
    __syncthreads();
    if (t == 0) {
        float tot = 0.f;
#pragma unroll
        for (int w = 0; w < 8; ++w) tot += red[w];
        g_xbg[k] = tot + linb[k];
    }
}

/* ---- conv3: chunk-split, division-free staging, padded smem -------------- */
#define C3S_SMEM ((64 * 388 + 576 + 576) * 4 + 64 * 4)

__global__ __launch_bounds__(256) void conv3s_kernel(
    const float* __restrict__ w3, const float* __restrict__ b3)
{
    int p = blockIdx.y;
    if (!g_nz[p]) return;
    extern __shared__ float sm[];
    float* y2h = sm;                   /* [ci][8*48 +pad4] */
    float* w3s = sm + 64 * 388;
    float* bgc = w3s + 576;
    int*  anch = (int*)(bgc + 576);
    int t = threadIdx.x;
    for (int i = t; i < 576; i += 256) { w3s[i] = w3[i]; bgc[i] = g_bg2c[i]; }
    if (t < 60) anch[t] = g_anchor[p * 60 + t];
    float b3v = __ldg(&b3[0]);
    const float* y2p = g_y2s + (size_t)p * C2C * (NA * W);

    int c0 = blockIdx.x * 6;
    {
        __syncthreads();
        {
            int ciS = t >> 2, tq = t & 3;
            const float* srcci = y2p + (size_t)ciS * (NA * W);
            float* dstci = y2h + ciS * 388;
#pragma unroll
            for (int r = 0; r < 8; ++r) {
                int a = c0 - 1 + r;
                bool rowok = (a >= 0) && (a < 60);
                int anA = rowok ? anch[a] : 0;
                int ry = (a == 0) ? 0 : ((a == 59) ? 2 : 1);
                const float* rowsrc = srcci + a * 32;
                float* rowdst = dstci + r * 48;
#pragma unroll
                for (int xi = tq; xi < 48; xi += 4) {
                    float v = 0.f;
                    if (rowok) {
                        int u = xi - 8;
                        int x = anA + u;
                        if (x >= 0 && x < 128) {
                            if (u >= 0 && u < 32) v = rowsrc[u];
                            else {
                                int rx = (x == 0) ? 0 : ((x == 127) ? 2 : 1);
                                v = bgc[(ry * 3 + rx) * 64 + ciS];
                            }
                        }
                    }
                    rowdst[xi] = v;
                }
            }
        }
        __syncthreads();
        if (t < 192) {
            int r = t >> 5, u = t & 31;
            int a = c0 + r;
            int anca = anch[a];
            float s = b3v;
#pragma unroll
            for (int dy = 0; dy < 3; ++dy) {
                int ar = a - 1 + dy;
                int du = anca - ((ar >= 0 && ar < 60) ? anch[ar] : anca);
                int bi = 8 + du + u - 1;
                if (bi < 0) bi = 0; if (bi > 45) bi = 45;
                for (int ci = 0; ci < 64; ++ci) {
                    const float* rp = y2h + ci * 388 + (r + dy) * 48 + bi;
                    s += w3s[ci * 9 + dy * 3 + 0] * rp[0]
                       + w3s[ci * 9 + dy * 3 + 1] * rp[1]
                       + w3s[ci * 9 + dy * 3 + 2] * rp[2];
                }
            }
            g_y3s[p * (NA * W) + a * 32 + u] = s;
        }
    }
}

/* --------------------- gather: patches = x_bg + lin·Δ ---------------------- */
__global__ __launch_bounds__(256) void gather_kernel(const float* __restrict__ linw) {
    __shared__ float diff[NA * W];
    __shared__ int anch[60];
    int p = blockIdx.x, t = threadIdx.x;
    if (!g_nz[p]) { if (t < 25) g_patches[p * 25 + t] = g_xbg[t]; return; }
    if (t < 60) anch[t] = g_anchor[p * 60 + t];
    __syncthreads();
    for (int e = t; e < NA * W; e += 256) {
        int a = e >> 5, u = e & 31;
        diff[e] = g_y3s[p * (NA * W) + e] - g_bg3[a * 128 + anch[a] + u];
    }
    __syncthreads();
    int warp = t >> 5, lane = t & 31;
    for (int k = warp; k < 25; k += 8) {
        const float* wk = linw + k * NPIX;
        float s = 0.f;
        for (int e = lane; e < NA * W; e += 32) {
            int a = e >> 5, u = e & 31;
            s += diff[e] * __ldg(&wk[a * 128 + anch[a] + u]);
        }
        for (int o = 16; o; o >>= 1) s += __shfl_down_sync(0xffffffffu, s, o);
        if (!lane) g_patches[p * 25 + k] = g_xbg[k] + s;
    }
}

/* ------------- recon: fused fill + scatter + sigmoid ----------------------- */
__global__ void recon_kernel(float* __restrict__ out) {
    int i = blockIdx.x * 256 + threadIdx.x;
    if (i >= IMGW * IMGW) return;
    int y = i >> 7, x = i & 127;
    float v = 0.5f;
    if (y < 125 && x < 125) {
        int py = y / 5, px = x / 5;
        int qy = y - py * 5, qx = x - px * 5;
        float z = g_patches[(py * 25 + px) * 25 + qy * 5 + qx];
        v = 1.f / (1.f + expf(-z));
    }
    out[i] = v;
}

/* ------------------------------- radon ------------------------------------- */
__global__ __launch_bounds__(128) void radon_kernel(float* __restrict__ out) {
    int a = blockIdx.x, tid = threadIdx.x;
    double ang = (double)a * (M_PI / 180.0);
    float ct = (float)cos(ang), st = (float)sin(ang);
    float t = (float)tid - 63.5f;
    const float* img = out;
    float accum = 0.f;
    for (int ss = 0; ss < 128; ++ss) {
        float s = (float)ss - 63.5f;
        float x = 63.5f + t * ct - s * st;
        float y = 63.5f + t * st + s * ct;
        float fx = floorf(x), fy = floorf(y);
        int x0 = (int)fx, y0 = (int)fy;
        float wx = x - fx, wy = y - fy;
        float v00 = 0.f, v10 = 0.f, v01 = 0.f, v11 = 0.f;
        if (x0 >= 0 && x0 < 128 && y0 >= 0 && y0 < 128)         v00 = __ldg(&img[y0 * 128 + x0]);
        if (x0 + 1 >= 0 && x0 + 1 < 128 && y0 >= 0 && y0 < 128) v10 = __ldg(&img[y0 * 128 + x0 + 1]);
        if (x0 >= 0 && x0 < 128 && y0 + 1 >= 0 && y0 + 1 < 128) v01 = __ldg(&img[(y0 + 1) * 128 + x0]);
        if (x0 + 1 >= 0 && x0 + 1 < 128 && y0 + 1 >= 0 && y0 + 1 < 128)
            v11 = __ldg(&img[(y0 + 1) * 128 + x0 + 1]);
        accum += v00 * (1.f - wx) * (1.f - wy) + v10 * wx * (1.f - wy)
               + v01 * (1.f - wx) * wy + v11 * wx * wy;
    }
    out[IMGW * IMGW + a * 128 + tid] = accum;
}

/* ------------------------------- launch ------------------------------------ */
extern "C" void kernel_launch(void* const* d_in, const int* in_sizes, int n_in,
                              void* d_out, int out_size)
{
    const float* sino   = (const float*)d_in[0];
    const float* w1     = (const float*)d_in[1];
    const float* b1     = (const float*)d_in[2];
    const float* w2     = (const float*)d_in[3];
    const float* b2     = (const float*)d_in[4];
    const float* w3     = (const float*)d_in[5];
    const float* b3     = (const float*)d_in[6];
    const float* linw   = (const float*)d_in[7];
    const float* linb   = (const float*)d_in[8];
    const int*   masks  = (const int*)d_in[9];
    float* out = (float*)d_out;

    cudaFuncSetAttribute(conv2s_kernel, cudaFuncAttributeMaxDynamicSharedMemorySize, C2S_SMEM);
    cudaFuncSetAttribute(conv3s_kernel, cudaFuncAttributeMaxDynamicSharedMemorySize, C3S_SMEM);

    prep_kernel<<<73, 256>>>(w2, b1, b2);                       /* 0 */
    anchors_kernel<<<NP, 64>>>(masks);                          /* 1 */
    conv1s_kernel<<<NP, 256>>>(sino, masks, w1, b1);            /* 2 */
    conv2s_kernel<<<dim3(4, NP, 10), 192, C2S_SMEM>>>(b2);      /* 3 <- profiled */
    bg3_kernel<<<60, 128>>>(w3, b3);                            /* 4 */
    xbg_kernel<<<25, 256>>>(linw, linb);                        /* 5 */
    conv3s_kernel<<<dim3(10, NP), 256, C3S_SMEM>>>(w3, b3);     /* 6 */
    gather_kernel<<<NP, 256>>>(linw);                           /* 7 */
    recon_kernel<<<(IMGW * IMGW + 255) / 256, 256>>>(out);      /* 8 */
    radon_kernel<<<NA, 128>>>(out);                             /* 9 */
}

// round 11
// speedup vs baseline: 3.6796x; 1.1682x over previous
#include <cuda_runtime.h>
#include <math.h>

#define IMGW 128
#define NA   60
#define NPIX 7680
#define NP   625
#define C1C  32
#define C2C  64
#define W    32

/* ------------------- scratch (static device memory) ---------------------- */
__device__ float g_y1s[(size_t)NP * C1C * NA * W];   /* [p][ci][a][32] */
__device__ float g_y2s[(size_t)NP * C2C * NA * W];   /* [p][co][a][32] */
__device__ float g_y3s[NP * NA * W];                 /* [p][a][32] */
__device__ int   g_anchor[NP * NA];
__device__ int   g_nz[NP];
__device__ float g_w2p[C1C * 9 * C2C];               /* [ci*9+k][co] */
__device__ float g_c1[C1C];
__device__ float g_bg2c[9 * C2C];
__device__ float g_bg3[NPIX];
__device__ float g_xbg[25];
__device__ float g_patches[NP * 25];

typedef unsigned long long u64;
__device__ __forceinline__ u64 dup2(float v) {
    u64 r; asm("mov.b64 %0,{%1,%1};" : "=l"(r) : "f"(v)); return r;
}
__device__ __forceinline__ void fma2(u64 &d, u64 a, u64 b) {
    asm("fma.rn.f32x2 %0,%1,%2,%0;" : "+l"(d) : "l"(a), "l"(b));
}
__device__ __forceinline__ float2 unpk(u64 v) {
    float2 r; asm("mov.b64 {%0,%1},%2;" : "=f"(r.x), "=f"(r.y) : "l"(v)); return r;
}

/* -------------------------------- prep ------------------------------------ */
__global__ void prep_kernel(const float* __restrict__ w2,
                            const float* __restrict__ b1,
                            const float* __restrict__ b2) {
    int b = blockIdx.x, t = threadIdx.x;
    if (b < 72) {
        int i = b * 256 + t;
        int co = i / 288, r = i - co * 288;
        int ci = r / 9, k = r - ci * 9;
        g_w2p[(ci * 9 + k) * 64 + co] = w2[i];
        return;
    }
    __shared__ float c1s[32];
    if (t < 32) { float v = fmaxf(b1[t], 0.f); c1s[t] = v; g_c1[t] = v; }
    __syncthreads();
    for (int it = t; it < 576; it += 256) {
        int co = it & 63, cls = it >> 6;
        int ry = cls / 3, rx = cls - ry * 3;
        float s = b2[co];
        for (int ci = 0; ci < 32; ++ci) {
            float wsum = 0.f;
            for (int dy = 0; dy < 3; ++dy) {
                if (ry == 0 && dy == 0) continue;
                if (ry == 2 && dy == 2) continue;
                for (int dx = 0; dx < 3; ++dx) {
                    if (rx == 0 && dx == 0) continue;
                    if (rx == 2 && dx == 2) continue;
                    wsum += w2[co * 288 + ci * 9 + dy * 3 + dx];
                }
            }
            s += wsum * c1s[ci];
        }
        g_bg2c[cls * 64 + co] = fmaxf(s, 0.f);
    }
}

/* ------------------------------ anchors ----------------------------------- */
__global__ void anchors_kernel(const int* __restrict__ masks) {
    __shared__ int nzf;
    int p = blockIdx.x, t = threadIdx.x;
    if (t == 0) nzf = 0;
    __syncthreads();
    if (t < 60) {
        const int* mp = masks + p * NPIX + t * 128;
        int L = -1, R = -1;
        for (int x = 0; x < 128; x += 4) {
            int4 m = *(const int4*)(mp + x);
            if (m.x) { if (L < 0) L = x;     R = x; }
            if (m.y) { if (L < 0) L = x + 1; R = x + 1; }
            if (m.z) { if (L < 0) L = x + 2; R = x + 2; }
            if (m.w) { if (L < 0) L = x + 3; R = x + 3; }
        }
        int anc;
        if (L < 0) anc = 48;
        else {
            nzf = 1;
            int c = (L + R) >> 1;
            anc = c - 16; if (anc < 0) anc = 0; if (anc > 96) anc = 96;
        }
        g_anchor[p * 60 + t] = anc;
    }
    __syncthreads();
    if (t == 0) g_nz[p] = nzf;
}

/* ----------------- conv1 on strips (smem-staged scalar) -------------------- */
__global__ __launch_bounds__(256) void conv1s_kernel(
    const float* __restrict__ sino, const int* __restrict__ masks,
    const float* __restrict__ w1, const float* __restrict__ b1)
{
    int p = blockIdx.x;
    if (!g_nz[p]) return;
    __shared__ float ms[NPIX];
    __shared__ float w1s[288], b1s[32];
    __shared__ int anch[60];
    int t = threadIdx.x;
    for (int i = t; i < 288; i += 256) w1s[i] = w1[i];
    if (t < 32) b1s[t] = b1[t];
    if (t < 60) anch[t] = g_anchor[p * 60 + t];
    const int* mp = masks + p * NPIX;
    for (int i = t; i < NPIX; i += 256) ms[i] = sino[i] * (float)mp[i];
    __syncthreads();

    for (int e = t; e < NA * W; e += 256) {
        int a = e >> 5, u = e & 31;
        int x = anch[a] + u;
        float tap[9];
#pragma unroll
        for (int dy = 0; dy < 3; ++dy) {
            int aa = a + dy - 1;
#pragma unroll
            for (int dx = 0; dx < 3; ++dx) {
                int xx = x + dx - 1;
                float v = 0.f;
                if (aa >= 0 && aa < 60 && xx >= 0 && xx < 128) v = ms[aa * 128 + xx];
                tap[dy * 3 + dx] = v;
            }
        }
        float* op = g_y1s + (size_t)p * (C1C * NA * W) + e;
        for (int ci = 0; ci < 32; ++ci) {
            float s = b1s[ci];
#pragma unroll
            for (int k = 0; k < 9; ++k) s += w1s[ci * 9 + k] * tap[k];
            op[(size_t)ci * (NA * W)] = fmaxf(s, 0.f);
        }
    }
}

/* -- conv2: co-split x4, 6-row chunks, ci-double-buffered, 5 CTAs/SM ------- */
/* s_w 4608 + y1h 16*388=6208 + c1 32 = 10848 floats (~43.4KB) + 60 ints */
#define C2S_SMEM ((4608 + 16 * 388 + 32) * 4 + 60 * 4)

__global__ __launch_bounds__(192, 5) void conv2s_kernel(const float* __restrict__ b2)
{
    int p = blockIdx.y;
    if (!g_nz[p]) return;
    extern __shared__ float sm[];
    float* s_w  = sm;                 /* [ci*9+k][16 co-quarter] (all 32 ci) */
    float* y1h  = sm + 4608;          /* [16 ci][8*48 +pad4] — half of ci   */
    float* c1s  = y1h + 16 * 388;     /* 32 */
    int*   anch = (int*)(c1s + 32);   /* 60 */
    int tid = threadIdx.x;
    int coh = blockIdx.x * 16;

    for (int i = tid; i < 4608; i += 192)
        s_w[i] = g_w2p[(i >> 4) * 64 + coh + (i & 15)];
    if (tid < 60) anch[tid] = g_anchor[p * 60 + tid];
    if (tid >= 64 && tid < 96) c1s[tid - 64] = g_c1[tid - 64];
    __syncthreads();

    int rr   = tid >> 5;          /* 0..5 row within chunk */
    int lane = tid & 31;
    int cog  = (lane >> 3) * 4;   /* 4 co within quarter */
    int u0   = (lane & 7) * 4;    /* 4 x */

    const float* y1p = g_y1s + (size_t)p * (C1C * NA * W);

    float bofs[4];
#pragma unroll
    for (int c = 0; c < 4; ++c) bofs[c] = __ldg(&b2[coh + cog + c]);

    int c0 = blockIdx.z * 6;
    int base = 1 << 30;
#pragma unroll
    for (int r = -1; r <= 6; ++r) {
        int a = c0 + r; a = a < 0 ? 0 : (a > 59 ? 59 : a);
        base = min(base, anch[a]);
    }
    base -= 2;

    int a   = c0 + rr;
    int off = anch[a] - base;

    /* staging thread map: 12 threads per ci (192/16) */
    int ciS = tid / 12, tq = tid - ciS * 12;

    u64 acc[2][4];
#pragma unroll
    for (int c = 0; c < 2; ++c)
#pragma unroll
        for (int x = 0; x < 4; ++x) acc[c][x] = 0ULL;

#pragma unroll
    for (int h = 0; h < 2; ++h) {
        /* stage ci half [16h, 16h+16) — identical predicate as before */
        {
            int cig = 16 * h + ciS;
            const float* srcci = y1p + (size_t)cig * (NA * W);
            float c1v = c1s[cig];
            float* dstci = y1h + ciS * 388;
#pragma unroll
            for (int r = 0; r < 8; ++r) {
                int ar = c0 - 1 + r;
                bool rowok = (ar >= 0) && (ar < 60);
                int anA = rowok ? anch[ar] : 0;
                const float* rowsrc = srcci + ar * 32;
                float* rowdst = dstci + r * 48;
#pragma unroll
                for (int x = tq; x < 48; x += 12) {
                    int xx = base + x;
                    int u = xx - anA;
                    float v = 0.f;
                    if (rowok && xx >= 0 && xx < 128)
                        v = (u >= 0 && u < 32) ? rowsrc[u] : c1v;
                    rowdst[x] = v;
                }
            }
        }
        __syncthreads();

        for (int ci = 0; ci < 16; ++ci) {
            const float* cb = y1h + ci * 388 + rr * 48 + off + u0 - 1;
            int cig9 = (16 * h + ci) * 9;
#pragma unroll
            for (int dy = 0; dy < 3; ++dy) {
                const float* row = cb + dy * 48;
                u64 dv[6];
#pragma unroll
                for (int k = 0; k < 6; ++k) dv[k] = dup2(row[k]);
#pragma unroll
                for (int dx = 0; dx < 3; ++dx) {
                    const u64* wp = (const u64*)(s_w + (cig9 + dy * 3 + dx) * 16 + cog);
                    u64 w0 = wp[0], w1 = wp[1];
#pragma unroll
                    for (int x = 0; x < 4; ++x) {
                        fma2(acc[0][x], w0, dv[dx + x]);
                        fma2(acc[1][x], w1, dv[dx + x]);
                    }
                }
            }
        }
        __syncthreads();
    }

    float* ob = g_y2s + ((size_t)p * C2C + coh + cog) * (NA * W) + a * 32 + u0;
#pragma unroll
    for (int cp = 0; cp < 2; ++cp) {
        float blo = bofs[2 * cp], bhi = bofs[2 * cp + 1];
        float2 v0 = unpk(acc[cp][0]), v1 = unpk(acc[cp][1]);
        float2 v2 = unpk(acc[cp][2]), v3 = unpk(acc[cp][3]);
        *(float4*)(ob + (size_t)(2 * cp) * (NA * W)) =
            make_float4(fmaxf(v0.x + blo, 0.f), fmaxf(v1.x + blo, 0.f),
                        fmaxf(v2.x + blo, 0.f), fmaxf(v3.x + blo, 0.f));
        *(float4*)(ob + (size_t)(2 * cp + 1) * (NA * W)) =
            make_float4(fmaxf(v0.y + bhi, 0.f), fmaxf(v1.y + bhi, 0.f),
                        fmaxf(v2.y + bhi, 0.f), fmaxf(v3.y + bhi, 0.f));
    }
}

/* ------------------------- y3 background field ----------------------------- */
__global__ void bg3_kernel(const float* __restrict__ w3, const float* __restrict__ b3) {
    __shared__ float bg2s[576];
    int a = blockIdx.x, x = threadIdx.x;
    for (int i = x; i < 576; i += 128) bg2s[i] = g_bg2c[i];
    __syncthreads();
    float s = b3[0];
    for (int dy = 0; dy < 3; ++dy) {
        int aa = a + dy - 1; if (aa < 0 || aa >= 60) continue;
        int ry = (aa == 0) ? 0 : ((aa == 59) ? 2 : 1);
        for (int dx = 0; dx < 3; ++dx) {
            int xx = x + dx - 1; if (xx < 0 || xx >= 128) continue;
            int rx = (xx == 0) ? 0 : ((xx == 127) ? 2 : 1);
            const float* cp = bg2s + (ry * 3 + rx) * 64;
            int k = dy * 3 + dx;
            for (int ci = 0; ci < 64; ++ci) s += w3[ci * 9 + k] * cp[ci];
        }
    }
    g_bg3[a * 128 + x] = s;
}

/* ---------------------- x_bg = lin(y3_bg), 25 blocks ----------------------- */
__global__ void xbg_kernel(const float* __restrict__ linw, const float* __restrict__ linb) {
    __shared__ float red[8];
    int k = blockIdx.x, t = threadIdx.x;
    const float* wk = linw + k * NPIX;
    float s = 0.f;
    for (int n = t; n < NPIX; n += 256) s += g_bg3[n] * __ldg(&wk[n]);
    for (int o = 16; o; o >>= 1) s += __shfl_down_sync(0xffffffffu, s, o);
    if (!(t & 31)) red[t >> 5] = s;
    __syncthreads();
    if (t == 0) {
        float tot = 0.f;
#pragma unroll
        for (int w = 0; w < 8; ++w) tot += red[w];
        g_xbg[k] = tot + linb[k];
    }
}

/* ---- conv3: chunk-split, ci-double-buffered, 4 CTAs/SM ------------------- */
/* y2h 32*388=12416 + w3s 576 + bgc 576 = 13568 floats (~54.3KB) + 64 ints */
#define C3S_SMEM ((32 * 388 + 576 + 576) * 4 + 64 * 4)

__global__ __launch_bounds__(256, 4) void conv3s_kernel(
    const float* __restrict__ w3, const float* __restrict__ b3)
{
    int p = blockIdx.y;
    if (!g_nz[p]) return;
    extern __shared__ float sm[];
    float* y2h = sm;                   /* [32 ci][8*48 +pad4] — half of ci */
    float* w3s = sm + 32 * 388;
    float* bgc = w3s + 576;
    int*  anch = (int*)(bgc + 576);
    int t = threadIdx.x;
    for (int i = t; i < 576; i += 256) { w3s[i] = w3[i]; bgc[i] = g_bg2c[i]; }
    if (t < 60) anch[t] = g_anchor[p * 60 + t];
    float b3v = __ldg(&b3[0]);
    const float* y2p = g_y2s + (size_t)p * C2C * (NA * W);
    __syncthreads();

    int c0 = blockIdx.x * 6;
    int ciS = t >> 3, tq = t & 7;       /* 8 threads per ci (256/32) */

    float s = b3v;
    int r_ = t >> 5, u_ = t & 31;
    int a_ = c0 + r_;
    int anca = (t < 192) ? anch[a_] : 0;

#pragma unroll
    for (int h = 0; h < 2; ++h) {
        /* stage ci half [32h, 32h+32) */
        {
            int cig = 32 * h + ciS;
            const float* srcci = y2p + (size_t)cig * (NA * W);
            float* dstci = y2h + ciS * 388;
#pragma unroll
            for (int r = 0; r < 8; ++r) {
                int ar = c0 - 1 + r;
                bool rowok = (ar >= 0) && (ar < 60);
                int anA = rowok ? anch[ar] : 0;
                int ry = (ar == 0) ? 0 : ((ar == 59) ? 2 : 1);
                const float* rowsrc = srcci + ar * 32;
                float* rowdst = dstci + r * 48;
#pragma unroll
                for (int xi = tq; xi < 48; xi += 8) {
                    float v = 0.f;
                    if (rowok) {
                        int u = xi - 8;
                        int x = anA + u;
                        if (x >= 0 && x < 128) {
                            if (u >= 0 && u < 32) v = rowsrc[u];
                            else {
                                int rx = (x == 0) ? 0 : ((x == 127) ? 2 : 1);
                                v = bgc[(ry * 3 + rx) * 64 + cig];
                            }
                        }
                    }
                    rowdst[xi] = v;
                }
            }
        }
        __syncthreads();

        if (t < 192) {
#pragma unroll
            for (int dy = 0; dy < 3; ++dy) {
                int ar = a_ - 1 + dy;
                int du = anca - ((ar >= 0 && ar < 60) ? anch[ar] : anca);
                int bi = 8 + du + u_ - 1;
                if (bi < 0) bi = 0; if (bi > 45) bi = 45;
                for (int ci = 0; ci < 32; ++ci) {
                    const float* rp = y2h + ci * 388 + (r_ + dy) * 48 + bi;
                    int wi = (32 * h + ci) * 9 + dy * 3;
                    s += w3s[wi + 0] * rp[0]
                       + w3s[wi + 1] * rp[1]
                       + w3s[wi + 2] * rp[2];
                }
            }
        }
        __syncthreads();
    }
    if (t < 192) g_y3s[p * (NA * W) + a_ * 32 + u_] = s;
}

/* --------------------- gather: patches = x_bg + lin·Δ ---------------------- */
__global__ __launch_bounds__(256) void gather_kernel(const float* __restrict__ linw) {
    __shared__ float diff[NA * W];
    __shared__ int anch[60];
    int p = blockIdx.x, t = threadIdx.x;
    if (!g_nz[p]) { if (t < 25) g_patches[p * 25 + t] = g_xbg[t]; return; }
    if (t < 60) anch[t] = g_anchor[p * 60 + t];
    __syncthreads();
    for (int e = t; e < NA * W; e += 256) {
        int a = e >> 5, u = e & 31;
        diff[e] = g_y3s[p * (NA * W) + e] - g_bg3[a * 128 + anch[a] + u];
    }
    __syncthreads();
    int warp = t >> 5, lane = t & 31;
    for (int k = warp; k < 25; k += 8) {
        const float* wk = linw + k * NPIX;
        float s = 0.f;
        for (int e = lane; e < NA * W; e += 32) {
            int a = e >> 5, u = e & 31;
            s += diff[e] * __ldg(&wk[a * 128 + anch[a] + u]);
        }
        for (int o = 16; o; o >>= 1) s += __shfl_down_sync(0xffffffffu, s, o);
        if (!lane) g_patches[p * 25 + k] = g_xbg[k] + s;
    }
}

/* ------------- recon: fused fill + scatter + sigmoid ----------------------- */
__global__ void recon_kernel(float* __restrict__ out) {
    int i = blockIdx.x * 256 + threadIdx.x;
    if (i >= IMGW * IMGW) return;
    int y = i >> 7, x = i & 127;
    float v = 0.5f;
    if (y < 125 && x < 125) {
        int py = y / 5, px = x / 5;
        int qy = y - py * 5, qx = x - px * 5;
        float z = g_patches[(py * 25 + px) * 25 + qy * 5 + qx];
        v = 1.f / (1.f + expf(-z));
    }
    out[i] = v;
}

/* ------------------------------- radon ------------------------------------- */
__global__ __launch_bounds__(128) void radon_kernel(float* __restrict__ out) {
    int a = blockIdx.x, tid = threadIdx.x;
    double ang = (double)a * (M_PI / 180.0);
    float ct = (float)cos(ang), st = (float)sin(ang);
    float t = (float)tid - 63.5f;
    const float* img = out;
    float accum = 0.f;
    for (int ss = 0; ss < 128; ++ss) {
        float s = (float)ss - 63.5f;
        float x = 63.5f + t * ct - s * st;
        float y = 63.5f + t * st + s * ct;
        float fx = floorf(x), fy = floorf(y);
        int x0 = (int)fx, y0 = (int)fy;
        float wx = x - fx, wy = y - fy;
        float v00 = 0.f, v10 = 0.f, v01 = 0.f, v11 = 0.f;
        if (x0 >= 0 && x0 < 128 && y0 >= 0 && y0 < 128)         v00 = __ldg(&img[y0 * 128 + x0]);
        if (x0 + 1 >= 0 && x0 + 1 < 128 && y0 >= 0 && y0 < 128) v10 = __ldg(&img[y0 * 128 + x0 + 1]);
        if (x0 >= 0 && x0 < 128 && y0 + 1 >= 0 && y0 + 1 < 128) v01 = __ldg(&img[(y0 + 1) * 128 + x0]);
        if (x0 + 1 >= 0 && x0 + 1 < 128 && y0 + 1 >= 0 && y0 + 1 < 128)
            v11 = __ldg(&img[(y0 + 1) * 128 + x0 + 1]);
        accum += v00 * (1.f - wx) * (1.f - wy) + v10 * wx * (1.f - wy)
               + v01 * (1.f - wx) * wy + v11 * wx * wy;
    }
    out[IMGW * IMGW + a * 128 + tid] = accum;
}

/* ------------------------------- launch ------------------------------------ */
extern "C" void kernel_launch(void* const* d_in, const int* in_sizes, int n_in,
                              void* d_out, int out_size)
{
    const float* sino   = (const float*)d_in[0];
    const float* w1     = (const float*)d_in[1];
    const float* b1     = (const float*)d_in[2];
    const float* w2     = (const float*)d_in[3];
    const float* b2     = (const float*)d_in[4];
    const float* w3     = (const float*)d_in[5];
    const float* b3     = (const float*)d_in[6];
    const float* linw   = (const float*)d_in[7];
    const float* linb   = (const float*)d_in[8];
    const int*   masks  = (const int*)d_in[9];
    float* out = (float*)d_out;

    cudaFuncSetAttribute(conv2s_kernel, cudaFuncAttributeMaxDynamicSharedMemorySize, C2S_SMEM);
    cudaFuncSetAttribute(conv3s_kernel, cudaFuncAttributeMaxDynamicSharedMemorySize, C3S_SMEM);

    prep_kernel<<<73, 256>>>(w2, b1, b2);                       /* 0 */
    anchors_kernel<<<NP, 64>>>(masks);                          /* 1 */
    conv1s_kernel<<<NP, 256>>>(sino, masks, w1, b1);            /* 2 */
    conv2s_kernel<<<dim3(4, NP, 10), 192, C2S_SMEM>>>(b2);      /* 3 <- profiled */
    bg3_kernel<<<60, 128>>>(w3, b3);                            /* 4 */
    xbg_kernel<<<25, 256>>>(linw, linb);                        /* 5 */
    conv3s_kernel<<<dim3(10, NP), 256, C3S_SMEM>>>(w3, b3);     /* 6 */
    gather_kernel<<<NP, 256>>>(linw);                           /* 7 */
    recon_kernel<<<(IMGW * IMGW + 255) / 256, 256>>>(out);      /* 8 */
    radon_kernel<<<NA, 128>>>(out);                             /* 9 */
}